// round 2
// baseline (speedup 1.0000x reference)
#include <cuda_runtime.h>
#include <math.h>

#define N_NODES 50000
#define N_EDGES 600000
#define DD 128
#define BN_EPS 1e-5f

// ---------------- scratch (device globals; no allocation allowed) ----------------
__device__ float g_xbuf[(size_t)N_NODES * DD];   // layer activations (BN output of GC layers)
__device__ float g_agg [(size_t)N_NODES * DD];   // scatter-add accumulator
__device__ float g_h1  [(size_t)N_NODES * DD];   // MLP hidden
__device__ float g_h2  [(size_t)N_NODES * DD];   // MLP output (pre-BN, post-activation)
__device__ float g_stats[2 * DD];                // column sum / sumsq

// ---------------- zero agg + stats ----------------
__global__ void zero_kernel() {
    int idx = blockIdx.x * 256 + threadIdx.x;
    const int total4 = N_NODES * DD / 4;  // 1,600,000
    if (idx < total4) {
        ((float4*)g_agg)[idx] = make_float4(0.f, 0.f, 0.f, 0.f);
    }
    if (idx < 2 * DD) g_stats[idx] = 0.f;
}

// ---------------- scatter-add: agg[dst] += x[src] ----------------
// one warp per edge, each lane handles a float4 (32 lanes * 4 = 128 dims)
__global__ void __launch_bounds__(256) scatter_kernel(
    const float* __restrict__ xp, int use_xbuf,
    const int* __restrict__ src, const int* __restrict__ dst)
{
    const float* x = use_xbuf ? g_xbuf : xp;
    int t = blockIdx.x * 256 + threadIdx.x;
    int e = t >> 5;
    if (e >= N_EDGES) return;
    int lane = t & 31;
    int s = src[e];
    int d = dst[e];
    if ((unsigned)s >= N_NODES || (unsigned)d >= N_NODES) return;  // defensive
    float4 v = *(const float4*)(x + (size_t)s * DD + lane * 4);
    float* p = g_agg + (size_t)d * DD + lane * 4;
    asm volatile("red.global.add.v4.f32 [%0], {%1,%2,%3,%4};"
                 :: "l"(p), "f"(v.x), "f"(v.y), "f"(v.z), "f"(v.w)
                 : "memory");
}

// ---------------- GEMM: out = act(A @ W + bias) ----------------
// MODE 0: A = xin + agg, out = relu -> g_h1
// MODE 1: A = g_h1,      out = relu -> g_h2
// MODE 2: A = g_h1,      out = tanh -> g_h2
// Tile: BM=64, BN=128, K chunked by 32. 256 threads, 4x8 per thread.
template <int MODE>
__global__ void __launch_bounds__(256) gemm_kernel(
    const float* __restrict__ xp, int use_xbuf,
    const float* __restrict__ W, const float* __restrict__ bias)
{
    __shared__ float As[64][36];    // padded: avoids bank conflicts on As[m][k] reads
    __shared__ float Bs[32][128];

    const int tid   = threadIdx.x;
    const int mbase = blockIdx.x * 64;
    const int tn    = tid & 15;     // 16 n-threads * 8 cols
    const int tm    = tid >> 4;     // 16 m-threads * 4 rows

    float acc[4][8];
#pragma unroll
    for (int i = 0; i < 4; i++)
#pragma unroll
        for (int j = 0; j < 8; j++) acc[i][j] = 0.f;

    const float* A0;
    if (MODE == 0) A0 = use_xbuf ? g_xbuf : xp;
    else           A0 = g_h1;

    for (int kc = 0; kc < DD; kc += 32) {
        // load A tile: 64 rows x 32 k = 512 float4, 2 per thread
#pragma unroll
        for (int i = 0; i < 2; i++) {
            int idx = tid + i * 256;
            int row = idx >> 3;
            int c4  = (idx & 7) << 2;
            int m   = mbase + row;
            float4 v = make_float4(0.f, 0.f, 0.f, 0.f);
            if (m < N_NODES) {
                size_t off = (size_t)m * DD + kc + c4;
                v = *(const float4*)(A0 + off);
                if (MODE == 0) {
                    float4 a = *(const float4*)(g_agg + off);
                    v.x += a.x; v.y += a.y; v.z += a.z; v.w += a.w;
                }
            }
            *(float4*)&As[row][c4] = v;
        }
        // load B tile: 32 rows x 128 = 1024 float4, 4 per thread
#pragma unroll
        for (int i = 0; i < 4; i++) {
            int idx = tid + i * 256;
            int row = idx >> 5;
            int c4  = (idx & 31) << 2;
            *(float4*)&Bs[row][c4] = *(const float4*)(W + (size_t)(kc + row) * DD + c4);
        }
        __syncthreads();

#pragma unroll
        for (int kk = 0; kk < 32; kk++) {
            float a[4];
#pragma unroll
            for (int i = 0; i < 4; i++) a[i] = As[tm * 4 + i][kk];
            float4 b0 = *(float4*)&Bs[kk][tn * 8];
            float4 b1 = *(float4*)&Bs[kk][tn * 8 + 4];
            float b[8] = {b0.x, b0.y, b0.z, b0.w, b1.x, b1.y, b1.z, b1.w};
#pragma unroll
            for (int i = 0; i < 4; i++)
#pragma unroll
                for (int j = 0; j < 8; j++)
                    acc[i][j] += a[i] * b[j];
        }
        __syncthreads();
    }

    // epilogue
    const int n0 = tn * 8;
    float bs[8];
#pragma unroll
    for (int j = 0; j < 8; j++) bs[j] = __ldg(&bias[n0 + j]);

    float* Out = (MODE == 0) ? g_h1 : g_h2;
#pragma unroll
    for (int i = 0; i < 4; i++) {
        int m = mbase + tm * 4 + i;
        if (m < N_NODES) {
            float v[8];
#pragma unroll
            for (int j = 0; j < 8; j++) {
                float t = acc[i][j] + bs[j];
                if (MODE == 2) t = tanhf(t);
                else           t = fmaxf(t, 0.f);
                v[j] = t;
            }
            *(float4*)(Out + (size_t)m * DD + n0)     = make_float4(v[0], v[1], v[2], v[3]);
            *(float4*)(Out + (size_t)m * DD + n0 + 4) = make_float4(v[4], v[5], v[6], v[7]);
        }
    }
}

// ---------------- column stats over g_h2 ----------------
__global__ void __launch_bounds__(256) stats_kernel() {
    const int col  = threadIdx.x & 127;
    const int half = threadIdx.x >> 7;
    float s = 0.f, ss = 0.f;
    for (int r = blockIdx.x * 2 + half; r < N_NODES; r += gridDim.x * 2) {
        float v = g_h2[(size_t)r * DD + col];
        s += v; ss += v * v;
    }
    __shared__ float sh[2 * DD];
    if (half == 0) { sh[col] = s; sh[DD + col] = ss; }
    __syncthreads();
    if (half == 1) {
        atomicAdd(&g_stats[col],      s  + sh[col]);
        atomicAdd(&g_stats[DD + col], ss + sh[DD + col]);
    }
}

// ---------------- batchnorm normalize ----------------
__global__ void __launch_bounds__(256) bn_kernel(
    const float* __restrict__ gamma, const float* __restrict__ beta,
    float* __restrict__ outp, int use_xbuf)
{
    __shared__ float sm_scale[DD], sm_shift[DD];
    int tid = threadIdx.x;
    if (tid < DD) {
        float mean = g_stats[tid] * (1.0f / N_NODES);
        float var  = g_stats[DD + tid] * (1.0f / N_NODES) - mean * mean;
        float rstd = rsqrtf(var + BN_EPS);
        float g = gamma[tid], b = beta[tid];
        sm_scale[tid] = rstd * g;
        sm_shift[tid] = b - mean * rstd * g;
    }
    __syncthreads();
    float* o = use_xbuf ? g_xbuf : outp;
    int idx = blockIdx.x * 256 + tid;
    const int total4 = N_NODES * DD / 4;
    if (idx < total4) {
        float4 v = ((const float4*)g_h2)[idx];
        int c = (idx * 4) & (DD - 1);
        float4 r;
        r.x = v.x * sm_scale[c]     + sm_shift[c];
        r.y = v.y * sm_scale[c + 1] + sm_shift[c + 1];
        r.z = v.z * sm_scale[c + 2] + sm_shift[c + 2];
        r.w = v.w * sm_scale[c + 3] + sm_shift[c + 3];
        ((float4*)o)[idx] = r;
    }
}

// ---------------- launcher ----------------
extern "C" void kernel_launch(void* const* d_in, const int* in_sizes, int n_in,
                              void* d_out, int out_size)
{
    const float* x     = (const float*)d_in[0];
    const int*   ei    = (const int*)d_in[1];     // int32! (JAX x64 disabled downcasts int64)
    // d_in[2] = batch (unused, all zeros)
    const float* W1    = (const float*)d_in[3];
    const float* b1    = (const float*)d_in[4];
    const float* W2    = (const float*)d_in[5];
    const float* b2    = (const float*)d_in[6];
    const float* gamma = (const float*)d_in[7];
    const float* beta  = (const float*)d_in[8];
    float*       out   = (float*)d_out;

    const int* src = ei;
    const int* dst = ei + N_EDGES;

    const int ZG = (N_NODES * DD / 4 + 255) / 256;       // 6250
    const int SG = (N_EDGES * 32 + 255) / 256;           // 75000
    const int GG = (N_NODES + 63) / 64;                  // 782

    for (int l = 0; l < 7; l++) {
        int use_xbuf = (l > 0) ? 1 : 0;
        zero_kernel<<<ZG, 256>>>();
        scatter_kernel<<<SG, 256>>>(x, use_xbuf, src, dst);
        gemm_kernel<0><<<GG, 256>>>(x, use_xbuf, W1 + (size_t)l * DD * DD, b1 + (size_t)l * DD);
        if (l < 3)
            gemm_kernel<1><<<GG, 256>>>(nullptr, 0, W2 + (size_t)l * DD * DD, b2 + (size_t)l * DD);
        else
            gemm_kernel<2><<<GG, 256>>>(nullptr, 0, W2 + (size_t)l * DD * DD, b2 + (size_t)l * DD);
        stats_kernel<<<512, 256>>>();
        float* op = (l < 3) ? nullptr : (out + (size_t)(l - 3) * N_NODES * DD);
        bn_kernel<<<ZG, 256>>>(gamma + (size_t)l * DD, beta + (size_t)l * DD, op, (l < 3) ? 1 : 0);
    }
}

// round 4
// speedup vs baseline: 2.5122x; 2.5122x over previous
#include <cuda_runtime.h>
#include <math.h>

#define N_NODES 50000
#define N_EDGES 600000
#define DD 128
#define BN_EPS 1e-5f

// ---------------- scratch (device globals; no allocation allowed) ----------------
__device__ float g_xbuf[(size_t)N_NODES * DD];
__device__ float g_agg [(size_t)N_NODES * DD];
__device__ float g_h1  [(size_t)N_NODES * DD];
__device__ float g_h2  [(size_t)N_NODES * DD];
__device__ float g_stats[2 * DD];
// CSR scratch
__device__ int g_cnt [N_NODES];
__device__ int g_fill[N_NODES];
__device__ int g_off [N_NODES + 1];
__device__ int g_csr_src[N_EDGES];

// ================= CSR build (once per call) =================
__global__ void zero_cnt_kernel() {
    int i = blockIdx.x * 256 + threadIdx.x;
    if (i < N_NODES) { g_cnt[i] = 0; g_fill[i] = 0; }
}

__global__ void hist_kernel(const int* __restrict__ dst) {
    int e = blockIdx.x * 256 + threadIdx.x;
    if (e < N_EDGES) {
        int d = dst[e];
        if ((unsigned)d < N_NODES) atomicAdd(&g_cnt[d], 1);
    }
}

__global__ void __launch_bounds__(1024) scan_kernel() {
    const int C = (N_NODES + 1023) / 1024;  // 49
    int tid = threadIdx.x;
    int s = 0;
    for (int i = 0; i < C; i++) {
        int j = tid * C + i;
        if (j < N_NODES) s += g_cnt[j];
    }
    __shared__ int sm[1024];
    sm[tid] = s;
    __syncthreads();
    for (int d = 1; d < 1024; d <<= 1) {
        int v = (tid >= d) ? sm[tid - d] : 0;
        __syncthreads();
        sm[tid] += v;
        __syncthreads();
    }
    int run = sm[tid] - s;  // exclusive prefix
    for (int i = 0; i < C; i++) {
        int j = tid * C + i;
        if (j < N_NODES) { g_off[j] = run; run += g_cnt[j]; }
    }
    if (tid == 1023) g_off[N_NODES] = sm[1023];
}

__global__ void fill_kernel(const int* __restrict__ src, const int* __restrict__ dst) {
    int e = blockIdx.x * 256 + threadIdx.x;
    if (e < N_EDGES) {
        int d = dst[e];
        int s = src[e];
        if ((unsigned)d < N_NODES && (unsigned)s < N_NODES) {
            int p = g_off[d] + atomicAdd(&g_fill[d], 1);
            g_csr_src[p] = s;
        }
    }
}

// ================= aggregation: agg[i] = sum_{j in N(i)} x[j] =================
// one warp per node; each lane owns a float4 (32*4 = 128 dims). Also zeroes g_stats.
__global__ void __launch_bounds__(256) agg_kernel(const float* __restrict__ xp, int use_xbuf) {
    if (blockIdx.x == 0 && threadIdx.x < 2 * DD) g_stats[threadIdx.x] = 0.f;
    const float* x = use_xbuf ? g_xbuf : xp;
    int t = blockIdx.x * 256 + threadIdx.x;
    int node = t >> 5;
    if (node >= N_NODES) return;
    int lane = t & 31;
    int beg = g_off[node], end = g_off[node + 1];
    float4 acc = make_float4(0.f, 0.f, 0.f, 0.f);
    for (int i = beg; i < end; i++) {
        int s = g_csr_src[i];
        float4 v = *(const float4*)(x + (size_t)s * DD + lane * 4);
        acc.x += v.x; acc.y += v.y; acc.z += v.z; acc.w += v.w;
    }
    *(float4*)(g_agg + (size_t)node * DD + lane * 4) = acc;
}

// ================= GEMM: out = act(A @ W + bias) =================
// MODE 0: A = xin + agg -> relu -> g_h1
// MODE 1: A = g_h1      -> relu -> g_h2
// MODE 2: A = g_h1      -> tanh -> g_h2
// 128x128 tile, BK=16, 256 threads, 8x8 per thread, register-prefetch pipeline.
template <int MODE>
__global__ void __launch_bounds__(256) gemm_kernel(
    const float* __restrict__ xp, int use_xbuf,
    const float* __restrict__ W, const float* __restrict__ bias)
{
    __shared__ float As[16][128];   // [k][m] (transposed A tile)
    __shared__ float Bs[16][128];   // [k][n]

    const int tid   = threadIdx.x;
    const int mbase = blockIdx.x * 128;
    const int tm    = tid >> 4;     // 0..15
    const int tn    = tid & 15;     // 0..15

    const float* A0 = (MODE == 0) ? (use_xbuf ? g_xbuf : xp) : g_h1;

    // A-load coords: 2 float4/thread, covering 128 rows x 16 k
    const int am0 = tid >> 2;          // 0..63
    const int ac4 = (tid & 3) * 4;     // 0,4,8,12
    // B-load coords: 2 float4/thread, covering 16 rows x 128 n
    const int br0 = tid >> 5;          // 0..7
    const int bc4 = (tid & 31) * 4;

    float4 aReg[2], bReg[2];

    // prefetch chunk 0
#pragma unroll
    for (int i = 0; i < 2; i++) {
        int m = mbase + am0 + 64 * i;
        float4 v = make_float4(0.f, 0.f, 0.f, 0.f);
        if (m < N_NODES) {
            size_t off = (size_t)m * DD + ac4;
            v = *(const float4*)(A0 + off);
            if (MODE == 0) {
                float4 a = *(const float4*)(g_agg + off);
                v.x += a.x; v.y += a.y; v.z += a.z; v.w += a.w;
            }
        }
        aReg[i] = v;
        bReg[i] = *(const float4*)(W + (size_t)(br0 + 8 * i) * DD + bc4);
    }

    float acc[8][8];
#pragma unroll
    for (int i = 0; i < 8; i++)
#pragma unroll
        for (int j = 0; j < 8; j++) acc[i][j] = 0.f;

    for (int kc = 0; kc < DD; kc += 16) {
        // commit staged regs to smem
#pragma unroll
        for (int i = 0; i < 2; i++) {
            As[ac4 + 0][am0 + 64 * i] = aReg[i].x;
            As[ac4 + 1][am0 + 64 * i] = aReg[i].y;
            As[ac4 + 2][am0 + 64 * i] = aReg[i].z;
            As[ac4 + 3][am0 + 64 * i] = aReg[i].w;
            *(float4*)&Bs[br0 + 8 * i][bc4] = bReg[i];
        }
        __syncthreads();

        // prefetch next chunk
        if (kc + 16 < DD) {
            int kn = kc + 16;
#pragma unroll
            for (int i = 0; i < 2; i++) {
                int m = mbase + am0 + 64 * i;
                float4 v = make_float4(0.f, 0.f, 0.f, 0.f);
                if (m < N_NODES) {
                    size_t off = (size_t)m * DD + kn + ac4;
                    v = *(const float4*)(A0 + off);
                    if (MODE == 0) {
                        float4 a = *(const float4*)(g_agg + off);
                        v.x += a.x; v.y += a.y; v.z += a.z; v.w += a.w;
                    }
                }
                aReg[i] = v;
                bReg[i] = *(const float4*)(W + (size_t)(kn + br0 + 8 * i) * DD + bc4);
            }
        }

        // compute: 16 k-steps x 64 FMA, 4 LDS.128 per step
#pragma unroll
        for (int kk = 0; kk < 16; kk++) {
            float4 a0 = *(float4*)&As[kk][tm * 4];
            float4 a1 = *(float4*)&As[kk][64 + tm * 4];
            float4 b0 = *(float4*)&Bs[kk][tn * 4];
            float4 b1 = *(float4*)&Bs[kk][64 + tn * 4];
            float av[8] = {a0.x, a0.y, a0.z, a0.w, a1.x, a1.y, a1.z, a1.w};
            float bv[8] = {b0.x, b0.y, b0.z, b0.w, b1.x, b1.y, b1.z, b1.w};
#pragma unroll
            for (int i = 0; i < 8; i++)
#pragma unroll
                for (int j = 0; j < 8; j++)
                    acc[i][j] += av[i] * bv[j];
        }
        __syncthreads();
    }

    // epilogue
    float bsv[8];
#pragma unroll
    for (int j = 0; j < 4; j++) {
        bsv[j]     = __ldg(&bias[tn * 4 + j]);
        bsv[4 + j] = __ldg(&bias[64 + tn * 4 + j]);
    }
    float* Out = (MODE == 0) ? g_h1 : g_h2;
#pragma unroll
    for (int i = 0; i < 8; i++) {
        int m = mbase + ((i < 4) ? (tm * 4 + i) : (64 + tm * 4 + i - 4));
        if (m < N_NODES) {
            float v[8];
#pragma unroll
            for (int j = 0; j < 8; j++) {
                float tval = acc[i][j] + bsv[j];
                if (MODE == 2) tval = tanhf(tval);
                else           tval = fmaxf(tval, 0.f);
                v[j] = tval;
            }
            *(float4*)(Out + (size_t)m * DD + tn * 4)      = make_float4(v[0], v[1], v[2], v[3]);
            *(float4*)(Out + (size_t)m * DD + 64 + tn * 4) = make_float4(v[4], v[5], v[6], v[7]);
        }
    }
}

// ================= column stats over g_h2 =================
__global__ void __launch_bounds__(256) stats_kernel() {
    const int col  = threadIdx.x & 127;
    const int half = threadIdx.x >> 7;
    float s = 0.f, ss = 0.f;
    for (int r = blockIdx.x * 2 + half; r < N_NODES; r += gridDim.x * 2) {
        float v = g_h2[(size_t)r * DD + col];
        s += v; ss += v * v;
    }
    __shared__ float sh[2 * DD];
    if (half == 0) { sh[col] = s; sh[DD + col] = ss; }
    __syncthreads();
    if (half == 1) {
        atomicAdd(&g_stats[col],      s  + sh[col]);
        atomicAdd(&g_stats[DD + col], ss + sh[DD + col]);
    }
}

// ================= batchnorm normalize =================
__global__ void __launch_bounds__(256) bn_kernel(
    const float* __restrict__ gamma, const float* __restrict__ beta,
    float* __restrict__ outp, int use_xbuf)
{
    __shared__ float sm_scale[DD], sm_shift[DD];
    int tid = threadIdx.x;
    if (tid < DD) {
        float mean = g_stats[tid] * (1.0f / N_NODES);
        float var  = g_stats[DD + tid] * (1.0f / N_NODES) - mean * mean;
        float rstd = rsqrtf(var + BN_EPS);
        float g = gamma[tid], b = beta[tid];
        sm_scale[tid] = rstd * g;
        sm_shift[tid] = b - mean * rstd * g;
    }
    __syncthreads();
    float* o = use_xbuf ? g_xbuf : outp;
    int idx = blockIdx.x * 256 + tid;
    const int total4 = N_NODES * DD / 4;
    if (idx < total4) {
        float4 v = ((const float4*)g_h2)[idx];
        int c = (idx * 4) & (DD - 1);
        float4 r;
        r.x = v.x * sm_scale[c]     + sm_shift[c];
        r.y = v.y * sm_scale[c + 1] + sm_shift[c + 1];
        r.z = v.z * sm_scale[c + 2] + sm_shift[c + 2];
        r.w = v.w * sm_scale[c + 3] + sm_shift[c + 3];
        ((float4*)o)[idx] = r;
    }
}

// ================= launcher =================
extern "C" void kernel_launch(void* const* d_in, const int* in_sizes, int n_in,
                              void* d_out, int out_size)
{
    const float* x     = (const float*)d_in[0];
    const int*   ei    = (const int*)d_in[1];     // int32 (JAX x64 disabled)
    const float* W1    = (const float*)d_in[3];
    const float* b1    = (const float*)d_in[4];
    const float* W2    = (const float*)d_in[5];
    const float* b2    = (const float*)d_in[6];
    const float* gamma = (const float*)d_in[7];
    const float* beta  = (const float*)d_in[8];
    float*       out   = (float*)d_out;

    const int* src = ei;
    const int* dst = ei + N_EDGES;

    const int EG = (N_EDGES + 255) / 256;                // 2344
    const int NG = (N_NODES + 255) / 256;                // 196
    const int AG = (N_NODES * 32 + 255) / 256;           // 6250
    const int GG = (N_NODES + 127) / 128;                // 391
    const int BG = (N_NODES * DD / 4 + 255) / 256;       // 6250

    // one-time CSR build
    zero_cnt_kernel<<<NG, 256>>>();
    hist_kernel<<<EG, 256>>>(dst);
    scan_kernel<<<1, 1024>>>();
    fill_kernel<<<EG, 256>>>(src, dst);

    for (int l = 0; l < 7; l++) {
        int use_xbuf = (l > 0) ? 1 : 0;
        agg_kernel<<<AG, 256>>>(x, use_xbuf);
        gemm_kernel<0><<<GG, 256>>>(x, use_xbuf, W1 + (size_t)l * DD * DD, b1 + (size_t)l * DD);
        if (l < 3)
            gemm_kernel<1><<<GG, 256>>>(nullptr, 0, W2 + (size_t)l * DD * DD, b2 + (size_t)l * DD);
        else
            gemm_kernel<2><<<GG, 256>>>(nullptr, 0, W2 + (size_t)l * DD * DD, b2 + (size_t)l * DD);
        stats_kernel<<<512, 256>>>();
        float* op = (l < 3) ? nullptr : (out + (size_t)(l - 3) * N_NODES * DD);
        bn_kernel<<<BG, 256>>>(gamma + (size_t)l * DD, beta + (size_t)l * DD, op, (l < 3) ? 1 : 0);
    }
}

// round 7
// speedup vs baseline: 3.3144x; 1.3193x over previous
#include <cuda_runtime.h>
#include <cuda_bf16.h>
#include <math.h>
#include <stdint.h>

#define N_NODES 50000
#define N_EDGES 600000
#define DD 128
#define BN_EPS 1e-5f

// ---------------- scratch (device globals; no allocation allowed) ----------------
__device__ float g_xbuf[(size_t)N_NODES * DD];
__device__ float g_agg [(size_t)N_NODES * DD];
__device__ float g_h1  [(size_t)N_NODES * DD];
__device__ float g_h2  [(size_t)N_NODES * DD];
__device__ float g_stats[2 * DD];
// CSR scratch
__device__ int g_cnt [N_NODES];
__device__ int g_fill[N_NODES];
__device__ int g_off [N_NODES + 1];
__device__ int g_csr_src[N_EDGES];
// pre-packed bf16 weight fragment images: [14 mats][hi/lo][128*128] u16, in
// mma.sync B-fragment order: idx = (((ks*16 + n_sub)*32 + lane)*2 + reg)*2 + elem
__device__ unsigned short g_wimg[14][2][DD * DD];

static __device__ __forceinline__ unsigned short bfbits(float f) {
    __nv_bfloat16 h = __float2bfloat16(f);
    return *reinterpret_cast<unsigned short*>(&h);
}
static __device__ __forceinline__ float bf2f(unsigned short u) {
    __nv_bfloat16 h = *reinterpret_cast<__nv_bfloat16*>(&u);
    return __bfloat162float(h);
}
static __device__ __forceinline__ uint32_t pack_bf2(float f0, float f1) {
    return (uint32_t)bfbits(f0) | ((uint32_t)bfbits(f1) << 16);
}

// ================= CSR build =================
__global__ void zero_cnt_kernel() {
    int i = blockIdx.x * 256 + threadIdx.x;
    if (i < N_NODES) { g_cnt[i] = 0; g_fill[i] = 0; }
}
__global__ void hist_kernel(const int* __restrict__ dst) {
    int e = blockIdx.x * 256 + threadIdx.x;
    if (e < N_EDGES) {
        int d = dst[e];
        if ((unsigned)d < N_NODES) atomicAdd(&g_cnt[d], 1);
    }
}
__global__ void __launch_bounds__(1024) scan_kernel() {
    const int C = (N_NODES + 1023) / 1024;
    int tid = threadIdx.x;
    int s = 0;
    for (int i = 0; i < C; i++) { int j = tid * C + i; if (j < N_NODES) s += g_cnt[j]; }
    __shared__ int sm[1024];
    sm[tid] = s;
    __syncthreads();
    for (int d = 1; d < 1024; d <<= 1) {
        int v = (tid >= d) ? sm[tid - d] : 0;
        __syncthreads();
        sm[tid] += v;
        __syncthreads();
    }
    int run = sm[tid] - s;
    for (int i = 0; i < C; i++) {
        int j = tid * C + i;
        if (j < N_NODES) { g_off[j] = run; run += g_cnt[j]; }
    }
    if (tid == 1023) g_off[N_NODES] = sm[1023];
}
__global__ void fill_kernel(const int* __restrict__ src, const int* __restrict__ dst) {
    int e = blockIdx.x * 256 + threadIdx.x;
    if (e < N_EDGES) {
        int d = dst[e];
        int s = src[e];
        if ((unsigned)d < N_NODES && (unsigned)s < N_NODES) {
            int p = g_off[d] + atomicAdd(&g_fill[d], 1);
            g_csr_src[p] = s;
        }
    }
}

// ================= weight convert: fp32 W[k][n] -> B-fragment images (hi/lo) =================
__global__ void wconv_kernel(const float* __restrict__ W1, const float* __restrict__ W2) {
    int t = blockIdx.x * 256 + threadIdx.x;
    if (t >= 14 * DD * DD) return;
    int mat = t >> 14;          // 0..13 (layer*2 + which)
    int e   = t & 16383;        // k*128 + n
    int k = e >> 7, n = e & 127;
    const float* Wsrc = (mat & 1) ? W2 : W1;
    float v = Wsrc[(size_t)(mat >> 1) * DD * DD + e];
    unsigned short hb = bfbits(v);
    unsigned short lb = bfbits(v - bf2f(hb));
    // B-fragment coords for mma.m16n8k16 (row.col):
    int ks = k >> 4, kk = k & 15;
    int ns = n >> 3, nn = n & 7;
    int lane = nn * 4 + ((kk & 7) >> 1);
    int reg  = kk >> 3;
    int elem = kk & 1;
    int idx = ((((ks * 16 + ns) * 32 + lane) * 2 + reg) * 2 + elem);
    g_wimg[mat][0][idx] = hb;
    g_wimg[mat][1][idx] = lb;
}

// ================= aggregation (CSR gather) =================
__global__ void __launch_bounds__(256) agg_kernel(const float* __restrict__ xp, int use_xbuf) {
    if (blockIdx.x == 0 && threadIdx.x < 2 * DD) g_stats[threadIdx.x] = 0.f;
    const float* x = use_xbuf ? g_xbuf : xp;
    int t = blockIdx.x * 256 + threadIdx.x;
    int node = t >> 5;
    if (node >= N_NODES) return;
    int lane = t & 31;
    int beg = g_off[node], end = g_off[node + 1];
    float4 acc = make_float4(0.f, 0.f, 0.f, 0.f);
    for (int i = beg; i < end; i++) {
        int s = g_csr_src[i];
        float4 v = *(const float4*)(x + (size_t)s * DD + lane * 4);
        acc.x += v.x; acc.y += v.y; acc.z += v.z; acc.w += v.w;
    }
    *(float4*)(g_agg + (size_t)node * DD + lane * 4) = acc;
}

// ================= tensor-core GEMM via mma.sync (bf16 x3 split) =================
// MODE 0: A = xin + agg -> relu -> g_h1
// MODE 1: A = g_h1      -> relu -> g_h2
// MODE 2: A = g_h1      -> tanh -> g_h2
// CTA: 128x128 tile; 8 warps = 4(m) x 2(n); warp tile 32x64.
// A staged in smem in A-fragment order; one LDS.128 per fragment.
#define FRAG_STRIDE 528   // 512B fragment + 16B pad (banks shift by 4 per frag)
#define A_MAT_BYTES (64 * FRAG_STRIDE)   // 64 fragments (8 m_sub x 8 ks)
#define SMEM_BYTES  (2 * A_MAT_BYTES)    // hi + lo

#define MMA_BF16(d, a, b) \
    asm volatile("mma.sync.aligned.m16n8k16.row.col.f32.bf16.bf16.f32 " \
                 "{%0,%1,%2,%3},{%4,%5,%6,%7},{%8,%9},{%0,%1,%2,%3};" \
                 : "+f"(d[0]), "+f"(d[1]), "+f"(d[2]), "+f"(d[3]) \
                 : "r"(a.x), "r"(a.y), "r"(a.z), "r"(a.w), "r"(b.x), "r"(b.y))

template <int MODE>
__global__ void __launch_bounds__(256) gemm_mma(
    const float* __restrict__ xp, int use_xbuf, int mat, const float* __restrict__ bias)
{
    extern __shared__ char smem[];
    const int tid  = threadIdx.x;
    const int wid  = tid >> 5;
    const int lane = tid & 31;
    const int mbase = blockIdx.x * 128;

    // ---- stage A: load fp32 (+agg), split bf16 hi/lo, write in fragment order ----
    const float* A0 = (MODE == 0) ? (use_xbuf ? g_xbuf : xp) : g_h1;
    const int rr  = tid >> 4;          // row within 16-row m_sub
    const int col = (tid & 15) * 8;    // 8-aligned k columns
    const int ks  = col >> 4;
    const int p   = ((rr & 15) >= 8 ? 1 : 0) + (((col & 15) >= 8) ? 2 : 0);
#pragma unroll
    for (int msub = 0; msub < 8; msub++) {
        int m = mbase + msub * 16 + rr;
        float v[8];
        if (m < N_NODES) {
            size_t off = (size_t)m * DD + col;
            float4 p0 = *(const float4*)(A0 + off);
            float4 p1 = *(const float4*)(A0 + off + 4);
            if (MODE == 0) {
                float4 a0 = *(const float4*)(g_agg + off);
                float4 a1 = *(const float4*)(g_agg + off + 4);
                p0.x += a0.x; p0.y += a0.y; p0.z += a0.z; p0.w += a0.w;
                p1.x += a1.x; p1.y += a1.y; p1.z += a1.z; p1.w += a1.w;
            }
            v[0] = p0.x; v[1] = p0.y; v[2] = p0.z; v[3] = p0.w;
            v[4] = p1.x; v[5] = p1.y; v[6] = p1.z; v[7] = p1.w;
        } else {
#pragma unroll
            for (int j = 0; j < 8; j++) v[j] = 0.f;
        }
        int fbase = (msub * 8 + ks) * FRAG_STRIDE + p * 4;
#pragma unroll
        for (int j = 0; j < 4; j++) {
            float f0 = v[2 * j], f1 = v[2 * j + 1];
            uint32_t hb0 = bfbits(f0), hb1 = bfbits(f1);
            uint32_t hp = hb0 | (hb1 << 16);
            uint32_t lp = pack_bf2(f0 - bf2f((unsigned short)hb0),
                                   f1 - bf2f((unsigned short)hb1));
            int lane_w = (rr & 7) * 4 + j;
            *(uint32_t*)(smem + fbase + lane_w * 16)               = hp;
            *(uint32_t*)(smem + A_MAT_BYTES + fbase + lane_w * 16) = lp;
        }
    }
    __syncthreads();

    // ---- MMA mainloop ----
    const int warp_m = wid >> 1;   // 0..3
    const int warp_n = wid & 1;    // 0..1
    float acc[2][8][4];
#pragma unroll
    for (int i = 0; i < 2; i++)
#pragma unroll
        for (int j = 0; j < 8; j++)
#pragma unroll
            for (int q = 0; q < 4; q++) acc[i][j][q] = 0.f;

    const uint2* wh = (const uint2*)&g_wimg[mat][0][0];
    const uint2* wl = (const uint2*)&g_wimg[mat][1][0];

#pragma unroll
    for (int k8 = 0; k8 < 8; k8++) {
        uint4 ah[2], al[2];
#pragma unroll
        for (int i = 0; i < 2; i++) {
            int fb = ((warp_m * 2 + i) * 8 + k8) * FRAG_STRIDE + lane * 16;
            ah[i] = *(const uint4*)(smem + fb);
            al[i] = *(const uint4*)(smem + A_MAT_BYTES + fb);
        }
        uint2 bh[8], bl[8];
#pragma unroll
        for (int ns = 0; ns < 8; ns++) {
            int bi = (k8 * 16 + warp_n * 8 + ns) * 32 + lane;
            bh[ns] = __ldg(&wh[bi]);
            bl[ns] = __ldg(&wl[bi]);
        }
#pragma unroll
        for (int ns = 0; ns < 8; ns++) {
            MMA_BF16(acc[0][ns], ah[0], bh[ns]);
            MMA_BF16(acc[1][ns], ah[1], bh[ns]);
            MMA_BF16(acc[0][ns], ah[0], bl[ns]);
            MMA_BF16(acc[1][ns], ah[1], bl[ns]);
            MMA_BF16(acc[0][ns], al[0], bh[ns]);
            MMA_BF16(acc[1][ns], al[1], bh[ns]);
        }
    }

    // ---- epilogue: bias + activation + store ----
    float* Out = (MODE == 0) ? g_h1 : g_h2;
#pragma unroll
    for (int i = 0; i < 2; i++) {
        int r0 = mbase + warp_m * 32 + i * 16 + (lane >> 2);
#pragma unroll
        for (int ns = 0; ns < 8; ns++) {
            int c = warp_n * 64 + ns * 8 + (lane & 3) * 2;
            float2 bv = *(const float2*)(bias + c);
            float o0 = acc[i][ns][0] + bv.x;
            float o1 = acc[i][ns][1] + bv.y;
            float o2 = acc[i][ns][2] + bv.x;
            float o3 = acc[i][ns][3] + bv.y;
            if (MODE == 2) {
                o0 = tanhf(o0); o1 = tanhf(o1); o2 = tanhf(o2); o3 = tanhf(o3);
            } else {
                o0 = fmaxf(o0, 0.f); o1 = fmaxf(o1, 0.f);
                o2 = fmaxf(o2, 0.f); o3 = fmaxf(o3, 0.f);
            }
            if (r0 < N_NODES)
                *(float2*)(Out + (size_t)r0 * DD + c) = make_float2(o0, o1);
            if (r0 + 8 < N_NODES)
                *(float2*)(Out + (size_t)(r0 + 8) * DD + c) = make_float2(o2, o3);
        }
    }
}

// ================= column stats over g_h2 =================
__global__ void __launch_bounds__(256) stats_kernel() {
    const int col  = threadIdx.x & 127;
    const int half = threadIdx.x >> 7;
    float s = 0.f, ss = 0.f;
    for (int r = blockIdx.x * 2 + half; r < N_NODES; r += gridDim.x * 2) {
        float v = g_h2[(size_t)r * DD + col];
        s += v; ss += v * v;
    }
    __shared__ float sh[2 * DD];
    if (half == 0) { sh[col] = s; sh[DD + col] = ss; }
    __syncthreads();
    if (half == 1) {
        atomicAdd(&g_stats[col],      s  + sh[col]);
        atomicAdd(&g_stats[DD + col], ss + sh[DD + col]);
    }
}

// ================= batchnorm normalize =================
__global__ void __launch_bounds__(256) bn_kernel(
    const float* __restrict__ gamma, const float* __restrict__ beta,
    float* __restrict__ outp, int use_xbuf)
{
    __shared__ float sm_scale[DD], sm_shift[DD];
    int tid = threadIdx.x;
    if (tid < DD) {
        float mean = g_stats[tid] * (1.0f / N_NODES);
        float var  = g_stats[DD + tid] * (1.0f / N_NODES) - mean * mean;
        float rstd = rsqrtf(var + BN_EPS);
        float g = gamma[tid], b = beta[tid];
        sm_scale[tid] = rstd * g;
        sm_shift[tid] = b - mean * rstd * g;
    }
    __syncthreads();
    float* o = use_xbuf ? g_xbuf : outp;
    int idx = blockIdx.x * 256 + tid;
    const int total4 = N_NODES * DD / 4;
    if (idx < total4) {
        float4 v = ((const float4*)g_h2)[idx];
        int c = (idx * 4) & (DD - 1);
        float4 r;
        r.x = v.x * sm_scale[c]     + sm_shift[c];
        r.y = v.y * sm_scale[c + 1] + sm_shift[c + 1];
        r.z = v.z * sm_scale[c + 2] + sm_shift[c + 2];
        r.w = v.w * sm_scale[c + 3] + sm_shift[c + 3];
        ((float4*)o)[idx] = r;
    }
}

// ================= launcher =================
extern "C" void kernel_launch(void* const* d_in, const int* in_sizes, int n_in,
                              void* d_out, int out_size)
{
    const float* x     = (const float*)d_in[0];
    const int*   ei    = (const int*)d_in[1];     // int32 (JAX x64 disabled)
    const float* W1    = (const float*)d_in[3];
    const float* b1    = (const float*)d_in[4];
    const float* W2    = (const float*)d_in[5];
    const float* b2    = (const float*)d_in[6];
    const float* gamma = (const float*)d_in[7];
    const float* beta  = (const float*)d_in[8];
    float*       out   = (float*)d_out;

    const int* src = ei;
    const int* dst = ei + N_EDGES;

    cudaFuncSetAttribute(gemm_mma<0>, cudaFuncAttributeMaxDynamicSharedMemorySize, SMEM_BYTES);
    cudaFuncSetAttribute(gemm_mma<1>, cudaFuncAttributeMaxDynamicSharedMemorySize, SMEM_BYTES);
    cudaFuncSetAttribute(gemm_mma<2>, cudaFuncAttributeMaxDynamicSharedMemorySize, SMEM_BYTES);

    const int EG = (N_EDGES + 255) / 256;
    const int NG = (N_NODES + 255) / 256;
    const int AG = (N_NODES * 32 + 255) / 256;
    const int GG = (N_NODES + 127) / 128;                // 391
    const int BG = (N_NODES * DD / 4 + 255) / 256;
    const int WG = (14 * DD * DD + 255) / 256;           // 896

    // one-time per-call prep
    zero_cnt_kernel<<<NG, 256>>>();
    hist_kernel<<<EG, 256>>>(dst);
    wconv_kernel<<<WG, 256>>>(W1, W2);
    scan_kernel<<<1, 1024>>>();
    fill_kernel<<<EG, 256>>>(src, dst);

    for (int l = 0; l < 7; l++) {
        int use_xbuf = (l > 0) ? 1 : 0;
        agg_kernel<<<AG, 256>>>(x, use_xbuf);
        gemm_mma<0><<<GG, 256, SMEM_BYTES>>>(x, use_xbuf, l * 2,     b1 + (size_t)l * DD);
        if (l < 3)
            gemm_mma<1><<<GG, 256, SMEM_BYTES>>>(nullptr, 0, l * 2 + 1, b2 + (size_t)l * DD);
        else
            gemm_mma<2><<<GG, 256, SMEM_BYTES>>>(nullptr, 0, l * 2 + 1, b2 + (size_t)l * DD);
        stats_kernel<<<512, 256>>>();
        float* op = (l < 3) ? nullptr : (out + (size_t)(l - 3) * N_NODES * DD);
        bn_kernel<<<BG, 256>>>(gamma + (size_t)l * DD, beta + (size_t)l * DD, op, (l < 3) ? 1 : 0);
    }
}

// round 9
// speedup vs baseline: 4.0367x; 1.2179x over previous
#include <cuda_runtime.h>
#include <cuda_bf16.h>
#include <math.h>
#include <stdint.h>

#define N_NODES 50000
#define N_EDGES 600000
#define DD 128
#define BN_EPS 1e-5f

// ---------------- scratch (device globals; no allocation allowed) ----------------
__device__ float g_xbuf[(size_t)N_NODES * DD];
__device__ float g_agg [(size_t)N_NODES * DD];
__device__ float g_h1  [(size_t)N_NODES * DD];
__device__ float g_h2  [(size_t)N_NODES * DD];
__device__ float g_statsL[7][2 * DD];            // per-layer column sum / sumsq
// CSR scratch
__device__ int g_cnt [N_NODES];
__device__ int g_fill[N_NODES];
__device__ int g_off [N_NODES + 1];
__device__ int g_bsum[256];
__device__ int g_csr_src[N_EDGES];
// pre-packed bf16 weight fragment images: [14 mats][hi/lo][128*128] u16, in
// mma.sync B-fragment order: idx = (((ks*16 + n_sub)*32 + lane)*2 + reg)*2 + elem
__device__ unsigned short g_wimg[14][2][DD * DD];

static __device__ __forceinline__ unsigned short bfbits(float f) {
    __nv_bfloat16 h = __float2bfloat16(f);
    return *reinterpret_cast<unsigned short*>(&h);
}
static __device__ __forceinline__ float bf2f(unsigned short u) {
    __nv_bfloat16 h = *reinterpret_cast<__nv_bfloat16*>(&u);
    return __bfloat162float(h);
}
static __device__ __forceinline__ uint32_t pack_bf2(float f0, float f1) {
    return (uint32_t)bfbits(f0) | ((uint32_t)bfbits(f1) << 16);
}

// ================= CSR build =================
__global__ void zero_cnt_kernel() {
    int i = blockIdx.x * 256 + threadIdx.x;
    if (i < N_NODES) { g_cnt[i] = 0; g_fill[i] = 0; }
    if (i < 7 * 2 * DD) ((float*)g_statsL)[i] = 0.f;
}
__global__ void hist_kernel(const int* __restrict__ dst) {
    int e = blockIdx.x * 256 + threadIdx.x;
    if (e < N_EDGES) {
        int d = dst[e];
        if ((unsigned)d < N_NODES) atomicAdd(&g_cnt[d], 1);
    }
}
// two-level scan: scan1 (per-block) -> scan2 (block sums) -> scan3 (add offsets)
__global__ void __launch_bounds__(256) scan1_kernel() {
    int t = threadIdx.x, b = blockIdx.x;
    int i = b * 256 + t;
    int v = (i < N_NODES) ? g_cnt[i] : 0;
    __shared__ int sm[256];
    sm[t] = v;
    __syncthreads();
#pragma unroll
    for (int d = 1; d < 256; d <<= 1) {
        int u = (t >= d) ? sm[t - d] : 0;
        __syncthreads();
        sm[t] += u;
        __syncthreads();
    }
    if (i <= N_NODES) g_off[i] = sm[t] - v;     // exclusive within block
    if (t == 255) g_bsum[b] = sm[255];
}
__global__ void __launch_bounds__(256) scan2_kernel(int nblocks) {
    int t = threadIdx.x;
    int v = (t < nblocks) ? g_bsum[t] : 0;
    __shared__ int sm[256];
    sm[t] = v;
    __syncthreads();
#pragma unroll
    for (int d = 1; d < 256; d <<= 1) {
        int u = (t >= d) ? sm[t - d] : 0;
        __syncthreads();
        sm[t] += u;
        __syncthreads();
    }
    if (t < nblocks) g_bsum[t] = sm[t] - v;     // exclusive block offsets
}
__global__ void __launch_bounds__(256) scan3_kernel() {
    int t = threadIdx.x, b = blockIdx.x;
    int i = b * 256 + t;
    if (i < N_NODES) {
        int o = g_off[i] + g_bsum[b];
        g_off[i] = o;
        if (i == N_NODES - 1) g_off[N_NODES] = o + g_cnt[i];
    }
}
__global__ void fill_kernel(const int* __restrict__ src, const int* __restrict__ dst) {
    int e = blockIdx.x * 256 + threadIdx.x;
    if (e < N_EDGES) {
        int d = dst[e];
        int s = src[e];
        if ((unsigned)d < N_NODES && (unsigned)s < N_NODES) {
            int p = g_off[d] + atomicAdd(&g_fill[d], 1);
            g_csr_src[p] = s;
        }
    }
}

// ================= weight convert: fp32 W[k][n] -> B-fragment images (hi/lo) =================
__global__ void wconv_kernel(const float* __restrict__ W1, const float* __restrict__ W2) {
    int t = blockIdx.x * 256 + threadIdx.x;
    if (t >= 14 * DD * DD) return;
    int mat = t >> 14;          // 0..13 (layer*2 + which)
    int e   = t & 16383;        // k*128 + n
    int k = e >> 7, n = e & 127;
    const float* Wsrc = (mat & 1) ? W2 : W1;
    float v = Wsrc[(size_t)(mat >> 1) * DD * DD + e];
    unsigned short hb = bfbits(v);
    unsigned short lb = bfbits(v - bf2f(hb));
    // B-fragment coords for mma.m16n8k16 (row.col):
    int ks = k >> 4, kk = k & 15;
    int ns = n >> 3, nn = n & 7;
    int lane = nn * 4 + ((kk & 7) >> 1);
    int reg  = kk >> 3;
    int elem = kk & 1;
    int idx = ((((ks * 16 + ns) * 32 + lane) * 2 + reg) * 2 + elem);
    g_wimg[mat][0][idx] = hb;
    g_wimg[mat][1][idx] = lb;
}

// ================= aggregation (CSR gather) =================
__global__ void __launch_bounds__(256) agg_kernel(const float* __restrict__ xp, int use_xbuf) {
    const float* x = use_xbuf ? g_xbuf : xp;
    int t = blockIdx.x * 256 + threadIdx.x;
    int node = t >> 5;
    if (node >= N_NODES) return;
    int lane = t & 31;
    int beg = g_off[node], end = g_off[node + 1];
    float4 acc = make_float4(0.f, 0.f, 0.f, 0.f);
    for (int i = beg; i < end; i++) {
        int s = g_csr_src[i];
        float4 v = *(const float4*)(x + (size_t)s * DD + lane * 4);
        acc.x += v.x; acc.y += v.y; acc.z += v.z; acc.w += v.w;
    }
    *(float4*)(g_agg + (size_t)node * DD + lane * 4) = acc;
}

// ================= tensor-core GEMM via mma.sync (bf16 x3 split) =================
// MODE 0: A = xin + agg -> relu -> g_h1            (no stats)
// MODE 1: A = g_h1      -> relu -> g_h2 (+stats)
// MODE 2: A = g_h1      -> tanh -> g_h2 (+stats)
// CTA: 128x128 tile; 8 warps = 4(m) x 2(n); warp tile 32x64.
#define FRAG_STRIDE 528   // 512B fragment + 16B pad
#define A_MAT_BYTES (64 * FRAG_STRIDE)   // 64 fragments (8 m_sub x 8 ks)
#define STAT_BYTES  1024                 // 256 floats: [0:128)=sum, [128:256)=sumsq
#define SMEM_BYTES  (2 * A_MAT_BYTES + STAT_BYTES)

#define MMA_BF16(d, a, b) \
    asm volatile("mma.sync.aligned.m16n8k16.row.col.f32.bf16.bf16.f32 " \
                 "{%0,%1,%2,%3},{%4,%5,%6,%7},{%8,%9},{%0,%1,%2,%3};" \
                 : "+f"(d[0]), "+f"(d[1]), "+f"(d[2]), "+f"(d[3]) \
                 : "r"(a.x), "r"(a.y), "r"(a.z), "r"(a.w), "r"(b.x), "r"(b.y))

template <int MODE>
__global__ void __launch_bounds__(256) gemm_mma(
    const float* __restrict__ xp, int use_xbuf, int mat,
    const float* __restrict__ bias, float* __restrict__ statsOut)
{
    extern __shared__ char smem[];
    float* sstat = (float*)(smem + 2 * A_MAT_BYTES);
    const int tid  = threadIdx.x;
    const int wid  = tid >> 5;
    const int lane = tid & 31;
    const int mbase = blockIdx.x * 128;

    if (MODE != 0) sstat[tid] = 0.f;

    // ---- stage A: load fp32 (+agg), split bf16 hi/lo, write in fragment order ----
    const float* A0 = (MODE == 0) ? (use_xbuf ? g_xbuf : xp) : g_h1;
    const int rr  = tid >> 4;          // row within 16-row m_sub
    const int col = (tid & 15) * 8;    // 8-aligned k columns
    const int ks  = col >> 4;
    const int p   = ((rr & 15) >= 8 ? 1 : 0) + (((col & 15) >= 8) ? 2 : 0);
#pragma unroll
    for (int msub = 0; msub < 8; msub++) {
        int m = mbase + msub * 16 + rr;
        float v[8];
        if (m < N_NODES) {
            size_t off = (size_t)m * DD + col;
            float4 p0 = *(const float4*)(A0 + off);
            float4 p1 = *(const float4*)(A0 + off + 4);
            if (MODE == 0) {
                float4 a0 = *(const float4*)(g_agg + off);
                float4 a1 = *(const float4*)(g_agg + off + 4);
                p0.x += a0.x; p0.y += a0.y; p0.z += a0.z; p0.w += a0.w;
                p1.x += a1.x; p1.y += a1.y; p1.z += a1.z; p1.w += a1.w;
            }
            v[0] = p0.x; v[1] = p0.y; v[2] = p0.z; v[3] = p0.w;
            v[4] = p1.x; v[5] = p1.y; v[6] = p1.z; v[7] = p1.w;
        } else {
#pragma unroll
            for (int j = 0; j < 8; j++) v[j] = 0.f;
        }
        int fbase = (msub * 8 + ks) * FRAG_STRIDE + p * 4;
#pragma unroll
        for (int j = 0; j < 4; j++) {
            float f0 = v[2 * j], f1 = v[2 * j + 1];
            uint32_t hb0 = bfbits(f0), hb1 = bfbits(f1);
            uint32_t hp = hb0 | (hb1 << 16);
            uint32_t lp = pack_bf2(f0 - bf2f((unsigned short)hb0),
                                   f1 - bf2f((unsigned short)hb1));
            int lane_w = (rr & 7) * 4 + j;
            *(uint32_t*)(smem + fbase + lane_w * 16)               = hp;
            *(uint32_t*)(smem + A_MAT_BYTES + fbase + lane_w * 16) = lp;
        }
    }
    __syncthreads();

    // ---- MMA mainloop ----
    const int warp_m = wid >> 1;   // 0..3
    const int warp_n = wid & 1;    // 0..1
    float acc[2][8][4];
#pragma unroll
    for (int i = 0; i < 2; i++)
#pragma unroll
        for (int j = 0; j < 8; j++)
#pragma unroll
            for (int q = 0; q < 4; q++) acc[i][j][q] = 0.f;

    const uint2* wh = (const uint2*)&g_wimg[mat][0][0];
    const uint2* wl = (const uint2*)&g_wimg[mat][1][0];

#pragma unroll
    for (int k8 = 0; k8 < 8; k8++) {
        uint4 ah[2], al[2];
#pragma unroll
        for (int i = 0; i < 2; i++) {
            int fb = ((warp_m * 2 + i) * 8 + k8) * FRAG_STRIDE + lane * 16;
            ah[i] = *(const uint4*)(smem + fb);
            al[i] = *(const uint4*)(smem + A_MAT_BYTES + fb);
        }
        uint2 bh[8], bl[8];
#pragma unroll
        for (int ns = 0; ns < 8; ns++) {
            int bi = (k8 * 16 + warp_n * 8 + ns) * 32 + lane;
            bh[ns] = __ldg(&wh[bi]);
            bl[ns] = __ldg(&wl[bi]);
        }
#pragma unroll
        for (int ns = 0; ns < 8; ns++) {
            MMA_BF16(acc[0][ns], ah[0], bh[ns]);
            MMA_BF16(acc[1][ns], ah[1], bh[ns]);
            MMA_BF16(acc[0][ns], ah[0], bl[ns]);
            MMA_BF16(acc[1][ns], ah[1], bl[ns]);
            MMA_BF16(acc[0][ns], al[0], bh[ns]);
            MMA_BF16(acc[1][ns], al[1], bh[ns]);
        }
    }

    // ---- epilogue: bias + activation + store (+ fused BN stats for MODE 1/2) ----
    float* Out = (MODE == 0) ? g_h1 : g_h2;
#pragma unroll
    for (int ns = 0; ns < 8; ns++) {
        int c = warp_n * 64 + ns * 8 + (lane & 3) * 2;
        float2 bv = *(const float2*)(bias + c);
        float s0 = 0.f, s1 = 0.f, q0 = 0.f, q1 = 0.f;
#pragma unroll
        for (int i = 0; i < 2; i++) {
            int r0 = mbase + warp_m * 32 + i * 16 + (lane >> 2);
            float o0 = acc[i][ns][0] + bv.x;
            float o1 = acc[i][ns][1] + bv.y;
            float o2 = acc[i][ns][2] + bv.x;
            float o3 = acc[i][ns][3] + bv.y;
            if (MODE == 2) {
                o0 = tanhf(o0); o1 = tanhf(o1); o2 = tanhf(o2); o3 = tanhf(o3);
            } else {
                o0 = fmaxf(o0, 0.f); o1 = fmaxf(o1, 0.f);
                o2 = fmaxf(o2, 0.f); o3 = fmaxf(o3, 0.f);
            }
            bool v0 = (r0 < N_NODES), v1 = (r0 + 8 < N_NODES);
            if (v0) *(float2*)(Out + (size_t)r0 * DD + c) = make_float2(o0, o1);
            if (v1) *(float2*)(Out + (size_t)(r0 + 8) * DD + c) = make_float2(o2, o3);
            if (MODE != 0) {
                if (v0) { s0 += o0; s1 += o1; q0 += o0 * o0; q1 += o1 * o1; }
                if (v1) { s0 += o2; s1 += o3; q0 += o2 * o2; q1 += o3 * o3; }
            }
        }
        if (MODE != 0) {
            // reduce over rows (lane bits 2..4), all lanes converge to group sum
#pragma unroll
            for (int off = 4; off <= 16; off <<= 1) {
                s0 += __shfl_xor_sync(0xffffffffu, s0, off);
                s1 += __shfl_xor_sync(0xffffffffu, s1, off);
                q0 += __shfl_xor_sync(0xffffffffu, q0, off);
                q1 += __shfl_xor_sync(0xffffffffu, q1, off);
            }
            if (lane < 4) {
                atomicAdd(&sstat[c],           s0);
                atomicAdd(&sstat[c + 1],       s1);
                atomicAdd(&sstat[128 + c],     q0);
                atomicAdd(&sstat[128 + c + 1], q1);
            }
        }
    }
    if (MODE != 0) {
        __syncthreads();
        atomicAdd(&statsOut[tid], sstat[tid]);
    }
}

// ================= batchnorm normalize =================
__global__ void __launch_bounds__(256) bn_kernel(
    const float* __restrict__ stats,
    const float* __restrict__ gamma, const float* __restrict__ beta,
    float* __restrict__ outp, int use_xbuf)
{
    __shared__ float sm_scale[DD], sm_shift[DD];
    int tid = threadIdx.x;
    if (tid < DD) {
        float mean = stats[tid] * (1.0f / N_NODES);
        float var  = stats[DD + tid] * (1.0f / N_NODES) - mean * mean;
        float rstd = rsqrtf(var + BN_EPS);
        float g = gamma[tid], b = beta[tid];
        sm_scale[tid] = rstd * g;
        sm_shift[tid] = b - mean * rstd * g;
    }
    __syncthreads();
    float* o = use_xbuf ? g_xbuf : outp;
    int idx = blockIdx.x * 256 + tid;
    const int total4 = N_NODES * DD / 4;
    if (idx < total4) {
        float4 v = ((const float4*)g_h2)[idx];
        int c = (idx * 4) & (DD - 1);
        float4 r;
        r.x = v.x * sm_scale[c]     + sm_shift[c];
        r.y = v.y * sm_scale[c + 1] + sm_shift[c + 1];
        r.z = v.z * sm_scale[c + 2] + sm_shift[c + 2];
        r.w = v.w * sm_scale[c + 3] + sm_shift[c + 3];
        ((float4*)o)[idx] = r;
    }
}

// ================= launcher =================
extern "C" void kernel_launch(void* const* d_in, const int* in_sizes, int n_in,
                              void* d_out, int out_size)
{
    const float* x     = (const float*)d_in[0];
    const int*   ei    = (const int*)d_in[1];     // int32 (JAX x64 disabled)
    const float* W1    = (const float*)d_in[3];
    const float* b1    = (const float*)d_in[4];
    const float* W2    = (const float*)d_in[5];
    const float* b2    = (const float*)d_in[6];
    const float* gamma = (const float*)d_in[7];
    const float* beta  = (const float*)d_in[8];
    float*       out   = (float*)d_out;

    const int* src = ei;
    const int* dst = ei + N_EDGES;

    cudaFuncSetAttribute(gemm_mma<0>, cudaFuncAttributeMaxDynamicSharedMemorySize, SMEM_BYTES);
    cudaFuncSetAttribute(gemm_mma<1>, cudaFuncAttributeMaxDynamicSharedMemorySize, SMEM_BYTES);
    cudaFuncSetAttribute(gemm_mma<2>, cudaFuncAttributeMaxDynamicSharedMemorySize, SMEM_BYTES);

    float* statsBase = nullptr;
    cudaGetSymbolAddress((void**)&statsBase, g_statsL);

    const int EG = (N_EDGES + 255) / 256;
    const int NG = (N_NODES + 255) / 256;                // 196
    const int AG = (N_NODES * 32 + 255) / 256;
    const int GG = (N_NODES + 127) / 128;                // 391
    const int BG = (N_NODES * DD / 4 + 255) / 256;
    const int WG = (14 * DD * DD + 255) / 256;           // 896

    // one-time per-call prep
    zero_cnt_kernel<<<NG, 256>>>();
    hist_kernel<<<EG, 256>>>(dst);
    wconv_kernel<<<WG, 256>>>(W1, W2);
    scan1_kernel<<<NG, 256>>>();
    scan2_kernel<<<1, 256>>>(NG);
    scan3_kernel<<<NG, 256>>>();
    fill_kernel<<<EG, 256>>>(src, dst);

    for (int l = 0; l < 7; l++) {
        int use_xbuf = (l > 0) ? 1 : 0;
        float* statsL = statsBase + l * 2 * DD;
        agg_kernel<<<AG, 256>>>(x, use_xbuf);
        gemm_mma<0><<<GG, 256, SMEM_BYTES>>>(x, use_xbuf, l * 2, b1 + (size_t)l * DD, nullptr);
        if (l < 3)
            gemm_mma<1><<<GG, 256, SMEM_BYTES>>>(nullptr, 0, l * 2 + 1, b2 + (size_t)l * DD, statsL);
        else
            gemm_mma<2><<<GG, 256, SMEM_BYTES>>>(nullptr, 0, l * 2 + 1, b2 + (size_t)l * DD, statsL);
        float* op = (l < 3) ? nullptr : (out + (size_t)(l - 3) * N_NODES * DD);
        bn_kernel<<<BG, 256>>>(statsL, gamma + (size_t)l * DD, beta + (size_t)l * DD, op, (l < 3) ? 1 : 0);
    }
}

// round 11
// speedup vs baseline: 4.5662x; 1.1312x over previous
#include <cuda_runtime.h>
#include <cuda_bf16.h>
#include <math.h>
#include <stdint.h>

#define N_NODES 50000
#define N_EDGES 600000
#define DD 128
#define BN_EPS 1e-5f
#define NTILES 391   // ceil(50000/128)

// ---------------- scratch (device globals; no allocation allowed) ----------------
__device__ float g_xbuf[(size_t)N_NODES * DD];
__device__ float g_agg [(size_t)N_NODES * DD];
__device__ float g_h1  [(size_t)N_NODES * DD];
__device__ float g_h2  [(size_t)N_NODES * DD];
__device__ float g_statsL[7][2 * DD];            // per-layer column sum / sumsq
// CSR scratch
__device__ int g_cnt [N_NODES];
__device__ int g_fill[N_NODES];
__device__ int g_off [N_NODES + 1];
__device__ int g_bsum[256];
__device__ int g_csr_src[N_EDGES];
// pre-packed bf16 weight fragment images: [14 mats][hi/lo][128*128] u16
__device__ unsigned short g_wimg[14][2][DD * DD];
// cached A fragments (hi/lo) for layers 3-6 first GEMM: per tile, 64 frags x 512B
__device__ unsigned char g_aimg[2][(size_t)NTILES * 64 * 512];

static __device__ __forceinline__ unsigned short bfbits(float f) {
    __nv_bfloat16 h = __float2bfloat16(f);
    return *reinterpret_cast<unsigned short*>(&h);
}
static __device__ __forceinline__ float bf2f(unsigned short u) {
    __nv_bfloat16 h = *reinterpret_cast<__nv_bfloat16*>(&u);
    return __bfloat162float(h);
}
static __device__ __forceinline__ uint32_t pack_bf2(float f0, float f1) {
    return (uint32_t)bfbits(f0) | ((uint32_t)bfbits(f1) << 16);
}

// ================= CSR build =================
__global__ void zero_cnt_kernel() {
    int i = blockIdx.x * 256 + threadIdx.x;
    if (i < N_NODES) { g_cnt[i] = 0; g_fill[i] = 0; }
    if (i < 7 * 2 * DD) ((float*)g_statsL)[i] = 0.f;
}
__global__ void hist_kernel(const int* __restrict__ dst) {
    int e = blockIdx.x * 256 + threadIdx.x;
    if (e < N_EDGES) {
        int d = dst[e];
        if ((unsigned)d < N_NODES) atomicAdd(&g_cnt[d], 1);
    }
}
__global__ void __launch_bounds__(256) scan1_kernel() {
    int t = threadIdx.x, b = blockIdx.x;
    int i = b * 256 + t;
    int v = (i < N_NODES) ? g_cnt[i] : 0;
    __shared__ int sm[256];
    sm[t] = v;
    __syncthreads();
#pragma unroll
    for (int d = 1; d < 256; d <<= 1) {
        int u = (t >= d) ? sm[t - d] : 0;
        __syncthreads();
        sm[t] += u;
        __syncthreads();
    }
    if (i <= N_NODES) g_off[i] = sm[t] - v;
    if (t == 255) g_bsum[b] = sm[255];
}
__global__ void __launch_bounds__(256) scan2_kernel(int nblocks) {
    int t = threadIdx.x;
    int v = (t < nblocks) ? g_bsum[t] : 0;
    __shared__ int sm[256];
    sm[t] = v;
    __syncthreads();
#pragma unroll
    for (int d = 1; d < 256; d <<= 1) {
        int u = (t >= d) ? sm[t - d] : 0;
        __syncthreads();
        sm[t] += u;
        __syncthreads();
    }
    if (t < nblocks) g_bsum[t] = sm[t] - v;
}
__global__ void __launch_bounds__(256) scan3_kernel() {
    int t = threadIdx.x, b = blockIdx.x;
    int i = b * 256 + t;
    if (i < N_NODES) {
        int o = g_off[i] + g_bsum[b];
        g_off[i] = o;
        if (i == N_NODES - 1) g_off[N_NODES] = o + g_cnt[i];
    }
}
__global__ void fill_kernel(const int* __restrict__ src, const int* __restrict__ dst) {
    int e = blockIdx.x * 256 + threadIdx.x;
    if (e < N_EDGES) {
        int d = dst[e];
        int s = src[e];
        if ((unsigned)d < N_NODES && (unsigned)s < N_NODES) {
            int p = g_off[d] + atomicAdd(&g_fill[d], 1);
            g_csr_src[p] = s;
        }
    }
}

// ================= weight convert: fp32 W[k][n] -> B-fragment images (hi/lo) =================
__global__ void wconv_kernel(const float* __restrict__ W1, const float* __restrict__ W2) {
    int t = blockIdx.x * 256 + threadIdx.x;
    if (t >= 14 * DD * DD) return;
    int mat = t >> 14;
    int e   = t & 16383;
    int k = e >> 7, n = e & 127;
    const float* Wsrc = (mat & 1) ? W2 : W1;
    float v = Wsrc[(size_t)(mat >> 1) * DD * DD + e];
    unsigned short hb = bfbits(v);
    unsigned short lb = bfbits(v - bf2f(hb));
    int ks = k >> 4, kk = k & 15;
    int ns = n >> 3, nn = n & 7;
    int lane = nn * 4 + ((kk & 7) >> 1);
    int reg  = kk >> 3;
    int elem = kk & 1;
    int idx = ((((ks * 16 + ns) * 32 + lane) * 2 + reg) * 2 + elem);
    g_wimg[mat][0][idx] = hb;
    g_wimg[mat][1][idx] = lb;
}

// ================= aggregation (CSR gather) =================
__global__ void __launch_bounds__(256) agg_kernel(const float* __restrict__ xp, int use_xbuf) {
    const float* x = use_xbuf ? g_xbuf : xp;
    int t = blockIdx.x * 256 + threadIdx.x;
    int node = t >> 5;
    if (node >= N_NODES) return;
    int lane = t & 31;
    int beg = g_off[node], end = g_off[node + 1];
    float4 acc = make_float4(0.f, 0.f, 0.f, 0.f);
    for (int i = beg; i < end; i++) {
        int s = g_csr_src[i];
        float4 v = *(const float4*)(x + (size_t)s * DD + lane * 4);
        acc.x += v.x; acc.y += v.y; acc.z += v.z; acc.w += v.w;
    }
    *(float4*)(g_agg + (size_t)node * DD + lane * 4) = acc;
}

// ================= tensor-core GEMM via mma.sync (bf16 x3 split) =================
// MODE 0: A = x(+agg)  -> relu -> g_h1              (layers 0-2 GEMM1)
// MODE 1: A = g_h1     -> relu -> g_h2 (+stats)     (layers 0-2 GEMM2)
// MODE 2: A = g_h1     -> tanh -> g_h2 (+stats)     (layers 3-6 GEMM2)
// MODE 3: like 0, also dump A-fragments to g_aimg   (layer 3 GEMM1)
// MODE 4: A from g_aimg -> relu -> g_h1 (no staging)(layers 4-6 GEMM1)
#define FRAG_STRIDE 528
#define A_MAT_BYTES (64 * FRAG_STRIDE)
#define STAT_BYTES  1024
#define SMEM_BYTES  (2 * A_MAT_BYTES + STAT_BYTES)

#define MMA_BF16(d, a, b) \
    asm volatile("mma.sync.aligned.m16n8k16.row.col.f32.bf16.bf16.f32 " \
                 "{%0,%1,%2,%3},{%4,%5,%6,%7},{%8,%9},{%0,%1,%2,%3};" \
                 : "+f"(d[0]), "+f"(d[1]), "+f"(d[2]), "+f"(d[3]) \
                 : "r"(a.x), "r"(a.y), "r"(a.z), "r"(a.w), "r"(b.x), "r"(b.y))

template <int MODE>
__global__ void __launch_bounds__(256) gemm_mma(
    const float* __restrict__ xp, int use_xbuf, int mat,
    const float* __restrict__ bias, float* __restrict__ statsOut)
{
    extern __shared__ char smem[];
    float* sstat = (float*)(smem + ((MODE == 4) ? 0 : 2 * A_MAT_BYTES));
    const int tid  = threadIdx.x;
    const int wid  = tid >> 5;
    const int lane = tid & 31;
    const int mbase = blockIdx.x * 128;

    if (MODE == 1 || MODE == 2) sstat[tid] = 0.f;

    if (MODE != 4) {
        // ---- stage A: load fp32 (+agg), split bf16 hi/lo, write in fragment order ----
        const float* A0 = (MODE == 0 || MODE == 3) ? (use_xbuf ? g_xbuf : xp) : g_h1;
        const int rr  = tid >> 4;
        const int col = (tid & 15) * 8;
        const int ks  = col >> 4;
        const int p   = ((rr & 15) >= 8 ? 1 : 0) + (((col & 15) >= 8) ? 2 : 0);
#pragma unroll
        for (int msub = 0; msub < 8; msub++) {
            int m = mbase + msub * 16 + rr;
            float v[8];
            if (m < N_NODES) {
                size_t off = (size_t)m * DD + col;
                float4 p0 = *(const float4*)(A0 + off);
                float4 p1 = *(const float4*)(A0 + off + 4);
                if (MODE == 0 || MODE == 3) {
                    float4 a0 = *(const float4*)(g_agg + off);
                    float4 a1 = *(const float4*)(g_agg + off + 4);
                    p0.x += a0.x; p0.y += a0.y; p0.z += a0.z; p0.w += a0.w;
                    p1.x += a1.x; p1.y += a1.y; p1.z += a1.z; p1.w += a1.w;
                }
                v[0] = p0.x; v[1] = p0.y; v[2] = p0.z; v[3] = p0.w;
                v[4] = p1.x; v[5] = p1.y; v[6] = p1.z; v[7] = p1.w;
            } else {
#pragma unroll
                for (int j = 0; j < 8; j++) v[j] = 0.f;
            }
            int frag = msub * 8 + ks;
            int fbase = frag * FRAG_STRIDE + p * 4;
            size_t gbase = ((size_t)blockIdx.x * 64 + frag) * 512 + p * 4;
#pragma unroll
            for (int j = 0; j < 4; j++) {
                float f0 = v[2 * j], f1 = v[2 * j + 1];
                uint32_t hb0 = bfbits(f0), hb1 = bfbits(f1);
                uint32_t hp = hb0 | (hb1 << 16);
                uint32_t lp = pack_bf2(f0 - bf2f((unsigned short)hb0),
                                       f1 - bf2f((unsigned short)hb1));
                int lane_w = (rr & 7) * 4 + j;
                *(uint32_t*)(smem + fbase + lane_w * 16)               = hp;
                *(uint32_t*)(smem + A_MAT_BYTES + fbase + lane_w * 16) = lp;
                if (MODE == 3) {
                    *(uint32_t*)(&g_aimg[0][gbase + lane_w * 16]) = hp;
                    *(uint32_t*)(&g_aimg[1][gbase + lane_w * 16]) = lp;
                }
            }
        }
        __syncthreads();
    }

    // ---- MMA mainloop ----
    const int warp_m = wid >> 1;
    const int warp_n = wid & 1;
    float acc[2][8][4];
#pragma unroll
    for (int i = 0; i < 2; i++)
#pragma unroll
        for (int j = 0; j < 8; j++)
#pragma unroll
            for (int q = 0; q < 4; q++) acc[i][j][q] = 0.f;

    const uint2* wh = (const uint2*)&g_wimg[mat][0][0];
    const uint2* wl = (const uint2*)&g_wimg[mat][1][0];

#pragma unroll
    for (int k8 = 0; k8 < 8; k8++) {
        uint4 ah[2], al[2];
#pragma unroll
        for (int i = 0; i < 2; i++) {
            int frag = ((warp_m * 2 + i) * 8 + k8);
            if (MODE == 4) {
                size_t gb = ((size_t)blockIdx.x * 64 + frag) * 512 + lane * 16;
                ah[i] = __ldg((const uint4*)&g_aimg[0][gb]);
                al[i] = __ldg((const uint4*)&g_aimg[1][gb]);
            } else {
                int fb = frag * FRAG_STRIDE + lane * 16;
                ah[i] = *(const uint4*)(smem + fb);
                al[i] = *(const uint4*)(smem + A_MAT_BYTES + fb);
            }
        }
        uint2 bh[8], bl[8];
#pragma unroll
        for (int ns = 0; ns < 8; ns++) {
            int bi = (k8 * 16 + warp_n * 8 + ns) * 32 + lane;
            bh[ns] = __ldg(&wh[bi]);
            bl[ns] = __ldg(&wl[bi]);
        }
#pragma unroll
        for (int ns = 0; ns < 8; ns++) {
            MMA_BF16(acc[0][ns], ah[0], bh[ns]);
            MMA_BF16(acc[1][ns], ah[1], bh[ns]);
            MMA_BF16(acc[0][ns], ah[0], bl[ns]);
            MMA_BF16(acc[1][ns], ah[1], bl[ns]);
            MMA_BF16(acc[0][ns], al[0], bh[ns]);
            MMA_BF16(acc[1][ns], al[1], bh[ns]);
        }
    }

    // ---- epilogue: bias + activation + store (+ fused BN stats) ----
    float* Out = (MODE == 1 || MODE == 2) ? g_h2 : g_h1;
#pragma unroll
    for (int ns = 0; ns < 8; ns++) {
        int c = warp_n * 64 + ns * 8 + (lane & 3) * 2;
        float2 bv = *(const float2*)(bias + c);
        float s0 = 0.f, s1 = 0.f, q0 = 0.f, q1 = 0.f;
#pragma unroll
        for (int i = 0; i < 2; i++) {
            int r0 = mbase + warp_m * 32 + i * 16 + (lane >> 2);
            float o0 = acc[i][ns][0] + bv.x;
            float o1 = acc[i][ns][1] + bv.y;
            float o2 = acc[i][ns][2] + bv.x;
            float o3 = acc[i][ns][3] + bv.y;
            if (MODE == 2) {
                o0 = tanhf(o0); o1 = tanhf(o1); o2 = tanhf(o2); o3 = tanhf(o3);
            } else {
                o0 = fmaxf(o0, 0.f); o1 = fmaxf(o1, 0.f);
                o2 = fmaxf(o2, 0.f); o3 = fmaxf(o3, 0.f);
            }
            bool v0 = (r0 < N_NODES), v1 = (r0 + 8 < N_NODES);
            if (v0) *(float2*)(Out + (size_t)r0 * DD + c) = make_float2(o0, o1);
            if (v1) *(float2*)(Out + (size_t)(r0 + 8) * DD + c) = make_float2(o2, o3);
            if (MODE == 1 || MODE == 2) {
                if (v0) { s0 += o0; s1 += o1; q0 += o0 * o0; q1 += o1 * o1; }
                if (v1) { s0 += o2; s1 += o3; q0 += o2 * o2; q1 += o3 * o3; }
            }
        }
        if (MODE == 1 || MODE == 2) {
#pragma unroll
            for (int off = 4; off <= 16; off <<= 1) {
                s0 += __shfl_xor_sync(0xffffffffu, s0, off);
                s1 += __shfl_xor_sync(0xffffffffu, s1, off);
                q0 += __shfl_xor_sync(0xffffffffu, q0, off);
                q1 += __shfl_xor_sync(0xffffffffu, q1, off);
            }
            if (lane < 4) {
                atomicAdd(&sstat[c],           s0);
                atomicAdd(&sstat[c + 1],       s1);
                atomicAdd(&sstat[128 + c],     q0);
                atomicAdd(&sstat[128 + c + 1], q1);
            }
        }
    }
    if (MODE == 1 || MODE == 2) {
        __syncthreads();
        atomicAdd(&statsOut[tid], sstat[tid]);
    }
}

// ================= batchnorm normalize =================
__global__ void __launch_bounds__(256) bn_kernel(
    const float* __restrict__ stats,
    const float* __restrict__ gamma, const float* __restrict__ beta,
    float* __restrict__ outp, int use_xbuf)
{
    __shared__ float sm_scale[DD], sm_shift[DD];
    int tid = threadIdx.x;
    if (tid < DD) {
        float mean = stats[tid] * (1.0f / N_NODES);
        float var  = stats[DD + tid] * (1.0f / N_NODES) - mean * mean;
        float rstd = rsqrtf(var + BN_EPS);
        float g = gamma[tid], b = beta[tid];
        sm_scale[tid] = rstd * g;
        sm_shift[tid] = b - mean * rstd * g;
    }
    __syncthreads();
    float* o = use_xbuf ? g_xbuf : outp;
    int idx = blockIdx.x * 256 + tid;
    const int total4 = N_NODES * DD / 4;
    if (idx < total4) {
        float4 v = ((const float4*)g_h2)[idx];
        int c = (idx * 4) & (DD - 1);
        float4 r;
        r.x = v.x * sm_scale[c]     + sm_shift[c];
        r.y = v.y * sm_scale[c + 1] + sm_shift[c + 1];
        r.z = v.z * sm_scale[c + 2] + sm_shift[c + 2];
        r.w = v.w * sm_scale[c + 3] + sm_shift[c + 3];
        ((float4*)o)[idx] = r;
    }
}

// ================= launcher =================
extern "C" void kernel_launch(void* const* d_in, const int* in_sizes, int n_in,
                              void* d_out, int out_size)
{
    const float* x     = (const float*)d_in[0];
    const int*   ei    = (const int*)d_in[1];     // int32 (JAX x64 disabled)
    const float* W1    = (const float*)d_in[3];
    const float* b1    = (const float*)d_in[4];
    const float* W2    = (const float*)d_in[5];
    const float* b2    = (const float*)d_in[6];
    const float* gamma = (const float*)d_in[7];
    const float* beta  = (const float*)d_in[8];
    float*       out   = (float*)d_out;

    const int* src = ei;
    const int* dst = ei + N_EDGES;

    cudaFuncSetAttribute(gemm_mma<0>, cudaFuncAttributeMaxDynamicSharedMemorySize, SMEM_BYTES);
    cudaFuncSetAttribute(gemm_mma<1>, cudaFuncAttributeMaxDynamicSharedMemorySize, SMEM_BYTES);
    cudaFuncSetAttribute(gemm_mma<2>, cudaFuncAttributeMaxDynamicSharedMemorySize, SMEM_BYTES);
    cudaFuncSetAttribute(gemm_mma<3>, cudaFuncAttributeMaxDynamicSharedMemorySize, SMEM_BYTES);

    float* statsBase = nullptr;
    cudaGetSymbolAddress((void**)&statsBase, g_statsL);

    const int EG = (N_EDGES + 255) / 256;
    const int NG = (N_NODES + 255) / 256;
    const int AG = (N_NODES * 32 + 255) / 256;
    const int GG = NTILES;
    const int BG = (N_NODES * DD / 4 + 255) / 256;
    const int WG = (14 * DD * DD + 255) / 256;

    // one-time per-call prep
    zero_cnt_kernel<<<NG, 256>>>();
    hist_kernel<<<EG, 256>>>(dst);
    wconv_kernel<<<WG, 256>>>(W1, W2);
    scan1_kernel<<<NG, 256>>>();
    scan2_kernel<<<1, 256>>>(NG);
    scan3_kernel<<<NG, 256>>>();
    fill_kernel<<<EG, 256>>>(src, dst);

    // ---- GC layers 0-2 ----
    for (int l = 0; l < 3; l++) {
        int use_xbuf = (l > 0) ? 1 : 0;
        float* statsL = statsBase + l * 2 * DD;
        agg_kernel<<<AG, 256>>>(x, use_xbuf);
        gemm_mma<0><<<GG, 256, SMEM_BYTES>>>(x, use_xbuf, l * 2, b1 + (size_t)l * DD, nullptr);
        gemm_mma<1><<<GG, 256, SMEM_BYTES>>>(nullptr, 0, l * 2 + 1, b2 + (size_t)l * DD, statsL);
        bn_kernel<<<BG, 256>>>(statsL, gamma + (size_t)l * DD, beta + (size_t)l * DD, nullptr, 1);
    }

    // ---- output layers 3-6: shared x (layer-2 BN output) -> shared agg ----
    agg_kernel<<<AG, 256>>>(nullptr, 1);
    for (int l = 3; l < 7; l++) {
        float* statsL = statsBase + l * 2 * DD;
        if (l == 3)
            gemm_mma<3><<<GG, 256, SMEM_BYTES>>>(nullptr, 1, l * 2, b1 + (size_t)l * DD, nullptr);
        else
            gemm_mma<4><<<GG, 256, STAT_BYTES>>>(nullptr, 1, l * 2, b1 + (size_t)l * DD, nullptr);
        gemm_mma<2><<<GG, 256, SMEM_BYTES>>>(nullptr, 0, l * 2 + 1, b2 + (size_t)l * DD, statsL);
        bn_kernel<<<BG, 256>>>(statsL, gamma + (size_t)l * DD, beta + (size_t)l * DD,
                               out + (size_t)(l - 3) * N_NODES * DD, 0);
    }
}

// round 13
// speedup vs baseline: 4.7431x; 1.0388x over previous
#include <cuda_runtime.h>
#include <cuda_bf16.h>
#include <math.h>
#include <stdint.h>

#define N_NODES 50000
#define N_EDGES 600000
#define DD 128
#define BN_EPS 1e-5f
#define NTILES 391   // ceil(50000/128)

// ---------------- scratch (device globals; no allocation allowed) ----------------
__device__ float g_agg [(size_t)N_NODES * DD];
__device__ float g_h1  [(size_t)N_NODES * DD];
__device__ float g_h2  [(size_t)N_NODES * DD];
__device__ float g_statsL[7][2 * DD];            // per-layer column sum / sumsq
// CSR scratch
__device__ int g_cnt [N_NODES];
__device__ int g_fill[N_NODES];
__device__ int g_off [N_NODES + 1];
__device__ int g_bsum[256];
__device__ int g_csr_src[N_EDGES];
// pre-packed bf16 weight fragment images: [14 mats][hi/lo][128*128] u16
__device__ unsigned short g_wimg[14][2][DD * DD];
// cached A fragments (hi/lo) for layers 3-6 first GEMM: per tile, 64 frags x 512B
__device__ unsigned char g_aimg[2][(size_t)NTILES * 64 * 512];

static __device__ __forceinline__ unsigned short bfbits(float f) {
    __nv_bfloat16 h = __float2bfloat16(f);
    return *reinterpret_cast<unsigned short*>(&h);
}
static __device__ __forceinline__ float bf2f(unsigned short u) {
    __nv_bfloat16 h = *reinterpret_cast<__nv_bfloat16*>(&u);
    return __bfloat162float(h);
}
static __device__ __forceinline__ uint32_t pack_bf2(float f0, float f1) {
    return (uint32_t)bfbits(f0) | ((uint32_t)bfbits(f1) << 16);
}

// ================= CSR build =================
__global__ void zero_cnt_kernel() {
    int i = blockIdx.x * 256 + threadIdx.x;
    if (i < N_NODES) { g_cnt[i] = 0; g_fill[i] = 0; }
    if (i < 7 * 2 * DD) ((float*)g_statsL)[i] = 0.f;
}
__global__ void hist_kernel(const int* __restrict__ dst) {
    int e = blockIdx.x * 256 + threadIdx.x;
    if (e < N_EDGES) {
        int d = dst[e];
        if ((unsigned)d < N_NODES) atomicAdd(&g_cnt[d], 1);
    }
}
__global__ void __launch_bounds__(256) scan1_kernel() {
    int t = threadIdx.x, b = blockIdx.x;
    int i = b * 256 + t;
    int v = (i < N_NODES) ? g_cnt[i] : 0;
    __shared__ int sm[256];
    sm[t] = v;
    __syncthreads();
#pragma unroll
    for (int d = 1; d < 256; d <<= 1) {
        int u = (t >= d) ? sm[t - d] : 0;
        __syncthreads();
        sm[t] += u;
        __syncthreads();
    }
    if (i <= N_NODES) g_off[i] = sm[t] - v;
    if (t == 255) g_bsum[b] = sm[255];
}
__global__ void __launch_bounds__(256) scan2_kernel(int nblocks) {
    int t = threadIdx.x;
    int v = (t < nblocks) ? g_bsum[t] : 0;
    __shared__ int sm[256];
    sm[t] = v;
    __syncthreads();
#pragma unroll
    for (int d = 1; d < 256; d <<= 1) {
        int u = (t >= d) ? sm[t - d] : 0;
        __syncthreads();
        sm[t] += u;
        __syncthreads();
    }
    if (t < nblocks) g_bsum[t] = sm[t] - v;
}
__global__ void __launch_bounds__(256) scan3_kernel() {
    int t = threadIdx.x, b = blockIdx.x;
    int i = b * 256 + t;
    if (i < N_NODES) {
        int o = g_off[i] + g_bsum[b];
        g_off[i] = o;
        if (i == N_NODES - 1) g_off[N_NODES] = o + g_cnt[i];
    }
}
__global__ void fill_kernel(const int* __restrict__ src, const int* __restrict__ dst) {
    int e = blockIdx.x * 256 + threadIdx.x;
    if (e < N_EDGES) {
        int d = dst[e];
        int s = src[e];
        if ((unsigned)d < N_NODES && (unsigned)s < N_NODES) {
            int p = g_off[d] + atomicAdd(&g_fill[d], 1);
            g_csr_src[p] = s;
        }
    }
}

// ================= weight convert: fp32 W[k][n] -> B-fragment images (hi/lo) =================
__global__ void wconv_kernel(const float* __restrict__ W1, const float* __restrict__ W2) {
    int t = blockIdx.x * 256 + threadIdx.x;
    if (t >= 14 * DD * DD) return;
    int mat = t >> 14;
    int e   = t & 16383;
    int k = e >> 7, n = e & 127;
    const float* Wsrc = (mat & 1) ? W2 : W1;
    float v = Wsrc[(size_t)(mat >> 1) * DD * DD + e];
    unsigned short hb = bfbits(v);
    unsigned short lb = bfbits(v - bf2f(hb));
    int ks = k >> 4, kk = k & 15;
    int ns = n >> 3, nn = n & 7;
    int lane = nn * 4 + ((kk & 7) >> 1);
    int reg  = kk >> 3;
    int elem = kk & 1;
    int idx = ((((ks * 16 + ns) * 32 + lane) * 2 + reg) * 2 + elem);
    g_wimg[mat][0][idx] = hb;
    g_wimg[mat][1][idx] = lb;
}

// ================= aggregation (CSR gather, raw sum) =================
__global__ void __launch_bounds__(256) agg_kernel(const float* __restrict__ x) {
    int t = blockIdx.x * 256 + threadIdx.x;
    int node = t >> 5;
    if (node >= N_NODES) return;
    int lane = t & 31;
    int beg = g_off[node], end = g_off[node + 1];
    float4 acc = make_float4(0.f, 0.f, 0.f, 0.f);
    for (int i = beg; i < end; i++) {
        int s = g_csr_src[i];
        float4 v = *(const float4*)(x + (size_t)s * DD + lane * 4);
        acc.x += v.x; acc.y += v.y; acc.z += v.z; acc.w += v.w;
    }
    *(float4*)(g_agg + (size_t)node * DD + lane * 4) = acc;
}

// ================= tensor-core GEMM via mma.sync (bf16 x3 split) =================
// MODE 0: A = affine(xin + agg, deg) -> relu -> g_h1   (GEMM1 of GC layers; bnstats may be null)
// MODE 1: A = g_h1 -> relu -> g_h2 (+stats)            (GEMM2 layers 0-2)
// MODE 2: A = g_h1 -> tanh -> outP (+stats)            (GEMM2 layers 3-6, writes d_out)
// MODE 3: like 0, also dump A-fragments to g_aimg      (layer 3 GEMM1)
// MODE 4: A from g_aimg -> relu -> g_h1                (layers 4-6 GEMM1)
#define FRAG_STRIDE 528
#define A_MAT_BYTES (64 * FRAG_STRIDE)
#define STAT_BYTES  1024
#define SMEM_BYTES  (2 * A_MAT_BYTES + STAT_BYTES)

#define MMA_BF16(d, a, b) \
    asm volatile("mma.sync.aligned.m16n8k16.row.col.f32.bf16.bf16.f32 " \
                 "{%0,%1,%2,%3},{%4,%5,%6,%7},{%8,%9},{%0,%1,%2,%3};" \
                 : "+f"(d[0]), "+f"(d[1]), "+f"(d[2]), "+f"(d[3]) \
                 : "r"(a.x), "r"(a.y), "r"(a.z), "r"(a.w), "r"(b.x), "r"(b.y))

template <int MODE>
__global__ void __launch_bounds__(256) gemm_mma(
    const float* __restrict__ xin, int mat,
    const float* __restrict__ bias, float* __restrict__ statsOut,
    const float* __restrict__ bnstats,
    const float* __restrict__ gammaL, const float* __restrict__ betaL,
    float* __restrict__ outP)
{
    extern __shared__ char smem[];
    float* sx = (float*)(smem + ((MODE == 4) ? 0 : 2 * A_MAT_BYTES));  // stats OR affine
    const int tid  = threadIdx.x;
    const int wid  = tid >> 5;
    const int lane = tid & 31;
    const int mbase = blockIdx.x * 128;

    if (MODE == 1 || MODE == 2) sx[tid] = 0.f;

    if (MODE == 0 || MODE == 3) {
        // per-column BN affine of the PREVIOUS layer (identity for layer 0)
        if (tid < DD) {
            float s = 1.f, t = 0.f;
            if (bnstats) {
                float mean = bnstats[tid] * (1.0f / N_NODES);
                float var  = bnstats[DD + tid] * (1.0f / N_NODES) - mean * mean;
                float rstd = rsqrtf(var + BN_EPS);
                s = gammaL[tid] * rstd;
                t = betaL[tid] - mean * s;
            }
            sx[tid] = s;
            sx[DD + tid] = t;
        }
        __syncthreads();
    }

    if (MODE != 4) {
        // ---- stage A: load fp32 (+agg, affine), split bf16 hi/lo, fragment order ----
        const float* A0 = (MODE == 0 || MODE == 3) ? xin : g_h1;
        const int rr  = tid >> 4;
        const int col = (tid & 15) * 8;
        const int ks  = col >> 4;
        const int p   = ((rr & 15) >= 8 ? 1 : 0) + (((col & 15) >= 8) ? 2 : 0);
        float sv[8], tv[8];
        if (MODE == 0 || MODE == 3) {
#pragma unroll
            for (int j = 0; j < 8; j++) { sv[j] = sx[col + j]; tv[j] = sx[DD + col + j]; }
        }
#pragma unroll
        for (int msub = 0; msub < 8; msub++) {
            int m = mbase + msub * 16 + rr;
            float v[8];
            if (m < N_NODES) {
                size_t off = (size_t)m * DD + col;
                float4 p0 = *(const float4*)(A0 + off);
                float4 p1 = *(const float4*)(A0 + off + 4);
                if (MODE == 0 || MODE == 3) {
                    float4 a0 = *(const float4*)(g_agg + off);
                    float4 a1 = *(const float4*)(g_agg + off + 4);
                    p0.x += a0.x; p0.y += a0.y; p0.z += a0.z; p0.w += a0.w;
                    p1.x += a1.x; p1.y += a1.y; p1.z += a1.z; p1.w += a1.w;
                    float cnt = 1.0f + (float)(g_off[m + 1] - g_off[m]);
                    v[0] = sv[0] * p0.x + cnt * tv[0];
                    v[1] = sv[1] * p0.y + cnt * tv[1];
                    v[2] = sv[2] * p0.z + cnt * tv[2];
                    v[3] = sv[3] * p0.w + cnt * tv[3];
                    v[4] = sv[4] * p1.x + cnt * tv[4];
                    v[5] = sv[5] * p1.y + cnt * tv[5];
                    v[6] = sv[6] * p1.z + cnt * tv[6];
                    v[7] = sv[7] * p1.w + cnt * tv[7];
                } else {
                    v[0] = p0.x; v[1] = p0.y; v[2] = p0.z; v[3] = p0.w;
                    v[4] = p1.x; v[5] = p1.y; v[6] = p1.z; v[7] = p1.w;
                }
            } else {
#pragma unroll
                for (int j = 0; j < 8; j++) v[j] = 0.f;
            }
            int frag = msub * 8 + ks;
            int fbase = frag * FRAG_STRIDE + p * 4;
            size_t gbase = ((size_t)blockIdx.x * 64 + frag) * 512 + p * 4;
#pragma unroll
            for (int j = 0; j < 4; j++) {
                float f0 = v[2 * j], f1 = v[2 * j + 1];
                uint32_t hb0 = bfbits(f0), hb1 = bfbits(f1);
                uint32_t hp = hb0 | (hb1 << 16);
                uint32_t lp = pack_bf2(f0 - bf2f((unsigned short)hb0),
                                       f1 - bf2f((unsigned short)hb1));
                int lane_w = (rr & 7) * 4 + j;
                *(uint32_t*)(smem + fbase + lane_w * 16)               = hp;
                *(uint32_t*)(smem + A_MAT_BYTES + fbase + lane_w * 16) = lp;
                if (MODE == 3) {
                    *(uint32_t*)(&g_aimg[0][gbase + lane_w * 16]) = hp;
                    *(uint32_t*)(&g_aimg[1][gbase + lane_w * 16]) = lp;
                }
            }
        }
        __syncthreads();
    }

    // ---- MMA mainloop ----
    const int warp_m = wid >> 1;
    const int warp_n = wid & 1;
    float acc[2][8][4];
#pragma unroll
    for (int i = 0; i < 2; i++)
#pragma unroll
        for (int j = 0; j < 8; j++)
#pragma unroll
            for (int q = 0; q < 4; q++) acc[i][j][q] = 0.f;

    const uint2* wh = (const uint2*)&g_wimg[mat][0][0];
    const uint2* wl = (const uint2*)&g_wimg[mat][1][0];

#pragma unroll
    for (int k8 = 0; k8 < 8; k8++) {
        uint4 ah[2], al[2];
#pragma unroll
        for (int i = 0; i < 2; i++) {
            int frag = ((warp_m * 2 + i) * 8 + k8);
            if (MODE == 4) {
                size_t gb = ((size_t)blockIdx.x * 64 + frag) * 512 + lane * 16;
                ah[i] = __ldg((const uint4*)&g_aimg[0][gb]);
                al[i] = __ldg((const uint4*)&g_aimg[1][gb]);
            } else {
                int fb = frag * FRAG_STRIDE + lane * 16;
                ah[i] = *(const uint4*)(smem + fb);
                al[i] = *(const uint4*)(smem + A_MAT_BYTES + fb);
            }
        }
        uint2 bh[8], bl[8];
#pragma unroll
        for (int ns = 0; ns < 8; ns++) {
            int bi = (k8 * 16 + warp_n * 8 + ns) * 32 + lane;
            bh[ns] = __ldg(&wh[bi]);
            bl[ns] = __ldg(&wl[bi]);
        }
#pragma unroll
        for (int ns = 0; ns < 8; ns++) {
            MMA_BF16(acc[0][ns], ah[0], bh[ns]);
            MMA_BF16(acc[1][ns], ah[1], bh[ns]);
            MMA_BF16(acc[0][ns], ah[0], bl[ns]);
            MMA_BF16(acc[1][ns], ah[1], bl[ns]);
            MMA_BF16(acc[0][ns], al[0], bh[ns]);
            MMA_BF16(acc[1][ns], al[1], bh[ns]);
        }
    }

    // ---- epilogue ----
    float* Out = (MODE == 1) ? g_h2 : ((MODE == 2) ? outP : g_h1);
#pragma unroll
    for (int ns = 0; ns < 8; ns++) {
        int c = warp_n * 64 + ns * 8 + (lane & 3) * 2;
        float2 bv = *(const float2*)(bias + c);
        float s0 = 0.f, s1 = 0.f, q0 = 0.f, q1 = 0.f;
#pragma unroll
        for (int i = 0; i < 2; i++) {
            int r0 = mbase + warp_m * 32 + i * 16 + (lane >> 2);
            float o0 = acc[i][ns][0] + bv.x;
            float o1 = acc[i][ns][1] + bv.y;
            float o2 = acc[i][ns][2] + bv.x;
            float o3 = acc[i][ns][3] + bv.y;
            if (MODE == 2) {
                o0 = tanhf(o0); o1 = tanhf(o1); o2 = tanhf(o2); o3 = tanhf(o3);
            } else {
                o0 = fmaxf(o0, 0.f); o1 = fmaxf(o1, 0.f);
                o2 = fmaxf(o2, 0.f); o3 = fmaxf(o3, 0.f);
            }
            bool v0 = (r0 < N_NODES), v1 = (r0 + 8 < N_NODES);
            if (v0) *(float2*)(Out + (size_t)r0 * DD + c) = make_float2(o0, o1);
            if (v1) *(float2*)(Out + (size_t)(r0 + 8) * DD + c) = make_float2(o2, o3);
            if (MODE == 1 || MODE == 2) {
                if (v0) { s0 += o0; s1 += o1; q0 += o0 * o0; q1 += o1 * o1; }
                if (v1) { s0 += o2; s1 += o3; q0 += o2 * o2; q1 += o3 * o3; }
            }
        }
        if (MODE == 1 || MODE == 2) {
#pragma unroll
            for (int off = 4; off <= 16; off <<= 1) {
                s0 += __shfl_xor_sync(0xffffffffu, s0, off);
                s1 += __shfl_xor_sync(0xffffffffu, s1, off);
                q0 += __shfl_xor_sync(0xffffffffu, q0, off);
                q1 += __shfl_xor_sync(0xffffffffu, q1, off);
            }
            if (lane < 4) {
                atomicAdd(&sx[c],           s0);
                atomicAdd(&sx[c + 1],       s1);
                atomicAdd(&sx[128 + c],     q0);
                atomicAdd(&sx[128 + c + 1], q1);
            }
        }
    }
    if (MODE == 1 || MODE == 2) {
        __syncthreads();
        atomicAdd(&statsOut[tid], sx[tid]);
    }
}

// ================= fused batchnorm for 4 output layers (in-place on d_out) =================
__global__ void __launch_bounds__(256) bn4_kernel(
    float* __restrict__ outp,
    const float* __restrict__ gamma, const float* __restrict__ beta)
{
    __shared__ float sm_scale[4 * DD], sm_shift[4 * DD];
    int tid = threadIdx.x;
    for (int i = tid; i < 4 * DD; i += 256) {
        int L = i >> 7, c = i & 127;
        const float* st = g_statsL[3 + L];
        float mean = st[c] * (1.0f / N_NODES);
        float var  = st[DD + c] * (1.0f / N_NODES) - mean * mean;
        float rstd = rsqrtf(var + BN_EPS);
        float g = gamma[(3 + L) * DD + c], b = beta[(3 + L) * DD + c];
        sm_scale[i] = rstd * g;
        sm_shift[i] = b - mean * rstd * g;
    }
    __syncthreads();
    const int per_layer4 = N_NODES * DD / 4;            // 1,600,000
    int idx = blockIdx.x * 256 + tid;
    if (idx < 4 * per_layer4) {
        int L = idx / per_layer4;
        int w = idx - L * per_layer4;
        int c = L * DD + ((w * 4) & (DD - 1));
        float4 v = ((const float4*)outp)[idx];
        float4 r;
        r.x = v.x * sm_scale[c]     + sm_shift[c];
        r.y = v.y * sm_scale[c + 1] + sm_shift[c + 1];
        r.z = v.z * sm_scale[c + 2] + sm_shift[c + 2];
        r.w = v.w * sm_scale[c + 3] + sm_shift[c + 3];
        ((float4*)outp)[idx] = r;
    }
}

// ================= launcher =================
extern "C" void kernel_launch(void* const* d_in, const int* in_sizes, int n_in,
                              void* d_out, int out_size)
{
    const float* x     = (const float*)d_in[0];
    const int*   ei    = (const int*)d_in[1];     // int32 (JAX x64 disabled)
    const float* W1    = (const float*)d_in[3];
    const float* b1    = (const float*)d_in[4];
    const float* W2    = (const float*)d_in[5];
    const float* b2    = (const float*)d_in[6];
    const float* gamma = (const float*)d_in[7];
    const float* beta  = (const float*)d_in[8];
    float*       out   = (float*)d_out;

    const int* src = ei;
    const int* dst = ei + N_EDGES;

    cudaFuncSetAttribute(gemm_mma<0>, cudaFuncAttributeMaxDynamicSharedMemorySize, SMEM_BYTES);
    cudaFuncSetAttribute(gemm_mma<1>, cudaFuncAttributeMaxDynamicSharedMemorySize, SMEM_BYTES);
    cudaFuncSetAttribute(gemm_mma<2>, cudaFuncAttributeMaxDynamicSharedMemorySize, SMEM_BYTES);
    cudaFuncSetAttribute(gemm_mma<3>, cudaFuncAttributeMaxDynamicSharedMemorySize, SMEM_BYTES);

    float* statsBase = nullptr;
    cudaGetSymbolAddress((void**)&statsBase, g_statsL);
    float* h2p = nullptr;
    cudaGetSymbolAddress((void**)&h2p, g_h2);

    const int EG = (N_EDGES + 255) / 256;
    const int NG = (N_NODES + 255) / 256;
    const int AG = (N_NODES * 32 + 255) / 256;
    const int GG = NTILES;
    const int WG = (14 * DD * DD + 255) / 256;
    const int B4 = (4 * N_NODES * DD / 4 + 255) / 256;   // 25000

    // one-time per-call prep
    zero_cnt_kernel<<<NG, 256>>>();
    hist_kernel<<<EG, 256>>>(dst);
    wconv_kernel<<<WG, 256>>>(W1, W2);
    scan1_kernel<<<NG, 256>>>();
    scan2_kernel<<<1, 256>>>(NG);
    scan3_kernel<<<NG, 256>>>();
    fill_kernel<<<EG, 256>>>(src, dst);

    // ---- GC layers 0-2 (BN folded into next layer's GEMM1 staging) ----
    for (int l = 0; l < 3; l++) {
        const float* xin = (l == 0) ? x : h2p;
        const float* bnst = (l == 0) ? nullptr : statsBase + (l - 1) * 2 * DD;
        const float* gmL = gamma + (size_t)(l - 1) * DD;   // only read when bnst != null
        const float* btL = beta + (size_t)(l - 1) * DD;
        agg_kernel<<<AG, 256>>>(xin);
        gemm_mma<0><<<GG, 256, SMEM_BYTES>>>(xin, l * 2, b1 + (size_t)l * DD,
                                             nullptr, bnst, gmL, btL, nullptr);
        gemm_mma<1><<<GG, 256, SMEM_BYTES>>>(nullptr, l * 2 + 1, b2 + (size_t)l * DD,
                                             statsBase + l * 2 * DD, nullptr, nullptr, nullptr, nullptr);
    }

    // ---- output layers 3-6: shared input (layer-2 h2 + BN affine) -> shared agg ----
    agg_kernel<<<AG, 256>>>(h2p);
    for (int l = 3; l < 7; l++) {
        if (l == 3)
            gemm_mma<3><<<GG, 256, SMEM_BYTES>>>(h2p, l * 2, b1 + (size_t)l * DD, nullptr,
                                                 statsBase + 2 * 2 * DD,
                                                 gamma + (size_t)2 * DD, beta + (size_t)2 * DD,
                                                 nullptr);
        else
            gemm_mma<4><<<GG, 256, STAT_BYTES>>>(nullptr, l * 2, b1 + (size_t)l * DD,
                                                 nullptr, nullptr, nullptr, nullptr, nullptr);
        gemm_mma<2><<<GG, 256, SMEM_BYTES>>>(nullptr, l * 2 + 1, b2 + (size_t)l * DD,
                                             statsBase + l * 2 * DD, nullptr, nullptr, nullptr,
                                             out + (size_t)(l - 3) * N_NODES * DD);
    }
    bn4_kernel<<<B4, 256>>>(out, gamma, beta);
}

// round 14
// speedup vs baseline: 4.7640x; 1.0044x over previous
#include <cuda_runtime.h>
#include <cuda_bf16.h>
#include <math.h>
#include <stdint.h>

#define N_NODES 50000
#define N_EDGES 600000
#define DD 128
#define BN_EPS 1e-5f
#define NTILES 391   // ceil(50000/128)

// ---------------- scratch (device globals; no allocation allowed) ----------------
__device__ float g_agg [(size_t)N_NODES * DD];
__device__ float g_h2  [(size_t)N_NODES * DD];
__device__ float g_statsL[7][2 * DD];            // per-layer column sum / sumsq
// CSR scratch
__device__ int g_cnt [N_NODES];
__device__ int g_fill[N_NODES];
__device__ int g_off [N_NODES + 1];
__device__ int g_bsum[256];
__device__ int g_csr_src[N_EDGES];
// pre-packed bf16 weight fragment images: [14 mats][hi/lo][128*128] u16
__device__ unsigned short g_wimg[14][2][DD * DD];
// cached A fragments (hi/lo) for layers 3-6 first GEMM: per tile, 64 frags x 512B
__device__ unsigned char g_aimg[2][(size_t)NTILES * 64 * 512];

static __device__ __forceinline__ unsigned short bfbits(float f) {
    __nv_bfloat16 h = __float2bfloat16(f);
    return *reinterpret_cast<unsigned short*>(&h);
}
static __device__ __forceinline__ float bf2f(unsigned short u) {
    __nv_bfloat16 h = *reinterpret_cast<__nv_bfloat16*>(&u);
    return __bfloat162float(h);
}
static __device__ __forceinline__ uint32_t pack_bf2(float f0, float f1) {
    return (uint32_t)bfbits(f0) | ((uint32_t)bfbits(f1) << 16);
}

// ================= CSR build =================
__global__ void zero_cnt_kernel() {
    int i = blockIdx.x * 256 + threadIdx.x;
    if (i < N_NODES) { g_cnt[i] = 0; g_fill[i] = 0; }
    if (i < 7 * 2 * DD) ((float*)g_statsL)[i] = 0.f;
}
__global__ void hist_kernel(const int* __restrict__ dst) {
    int e = blockIdx.x * 256 + threadIdx.x;
    if (e < N_EDGES) {
        int d = dst[e];
        if ((unsigned)d < N_NODES) atomicAdd(&g_cnt[d], 1);
    }
}
__global__ void __launch_bounds__(256) scan1_kernel() {
    int t = threadIdx.x, b = blockIdx.x;
    int i = b * 256 + t;
    int v = (i < N_NODES) ? g_cnt[i] : 0;
    __shared__ int sm[256];
    sm[t] = v;
    __syncthreads();
#pragma unroll
    for (int d = 1; d < 256; d <<= 1) {
        int u = (t >= d) ? sm[t - d] : 0;
        __syncthreads();
        sm[t] += u;
        __syncthreads();
    }
    if (i <= N_NODES) g_off[i] = sm[t] - v;
    if (t == 255) g_bsum[b] = sm[255];
}
__global__ void __launch_bounds__(256) scan2_kernel(int nblocks) {
    int t = threadIdx.x;
    int v = (t < nblocks) ? g_bsum[t] : 0;
    __shared__ int sm[256];
    sm[t] = v;
    __syncthreads();
#pragma unroll
    for (int d = 1; d < 256; d <<= 1) {
        int u = (t >= d) ? sm[t - d] : 0;
        __syncthreads();
        sm[t] += u;
        __syncthreads();
    }
    if (t < nblocks) g_bsum[t] = sm[t] - v;
}
__global__ void __launch_bounds__(256) scan3_kernel() {
    int t = threadIdx.x, b = blockIdx.x;
    int i = b * 256 + t;
    if (i < N_NODES) {
        int o = g_off[i] + g_bsum[b];
        g_off[i] = o;
        if (i == N_NODES - 1) g_off[N_NODES] = o + g_cnt[i];
    }
}
__global__ void fill_kernel(const int* __restrict__ src, const int* __restrict__ dst) {
    int e = blockIdx.x * 256 + threadIdx.x;
    if (e < N_EDGES) {
        int d = dst[e];
        int s = src[e];
        if ((unsigned)d < N_NODES && (unsigned)s < N_NODES) {
            int p = g_off[d] + atomicAdd(&g_fill[d], 1);
            g_csr_src[p] = s;
        }
    }
}

// ================= weight convert: fp32 W[k][n] -> B-fragment images (hi/lo) =================
__global__ void wconv_kernel(const float* __restrict__ W1, const float* __restrict__ W2) {
    int t = blockIdx.x * 256 + threadIdx.x;
    if (t >= 14 * DD * DD) return;
    int mat = t >> 14;
    int e   = t & 16383;
    int k = e >> 7, n = e & 127;
    const float* Wsrc = (mat & 1) ? W2 : W1;
    float v = Wsrc[(size_t)(mat >> 1) * DD * DD + e];
    unsigned short hb = bfbits(v);
    unsigned short lb = bfbits(v - bf2f(hb));
    int ks = k >> 4, kk = k & 15;
    int ns = n >> 3, nn = n & 7;
    int lane = nn * 4 + ((kk & 7) >> 1);
    int reg  = kk >> 3;
    int elem = kk & 1;
    int idx = ((((ks * 16 + ns) * 32 + lane) * 2 + reg) * 2 + elem);
    g_wimg[mat][0][idx] = hb;
    g_wimg[mat][1][idx] = lb;
}

// ================= aggregation (CSR gather, raw sum) =================
__global__ void __launch_bounds__(256) agg_kernel(const float* __restrict__ x) {
    int t = blockIdx.x * 256 + threadIdx.x;
    int node = t >> 5;
    if (node >= N_NODES) return;
    int lane = t & 31;
    int beg = g_off[node], end = g_off[node + 1];
    float4 acc = make_float4(0.f, 0.f, 0.f, 0.f);
    for (int i = beg; i < end; i++) {
        int s = g_csr_src[i];
        float4 v = *(const float4*)(x + (size_t)s * DD + lane * 4);
        acc.x += v.x; acc.y += v.y; acc.z += v.z; acc.w += v.w;
    }
    *(float4*)(g_agg + (size_t)node * DD + lane * 4) = acc;
}

// ================= fused layer kernel: out = act2((relu(A@W1+b1))@W2+b2) =================
// FMODE 0: A = affine(xin+agg,deg); act2=relu -> g_h2 (+stats)    (GC layers 0-2)
// FMODE 1: like 0 but dump A-frags to g_aimg; act2=tanh -> outP   (layer 3)
// FMODE 2: A from g_aimg; act2=tanh -> outP                       (layers 4-6)
#define FRAG_STRIDE 528
#define A_MAT_BYTES (64 * FRAG_STRIDE)
#define STAT_BYTES  1024
#define SMEM_BYTES  (2 * A_MAT_BYTES + STAT_BYTES)

#define MMA_BF16(d, a, b) \
    asm volatile("mma.sync.aligned.m16n8k16.row.col.f32.bf16.bf16.f32 " \
                 "{%0,%1,%2,%3},{%4,%5,%6,%7},{%8,%9},{%0,%1,%2,%3};" \
                 : "+f"(d[0]), "+f"(d[1]), "+f"(d[2]), "+f"(d[3]) \
                 : "r"(a.x), "r"(a.y), "r"(a.z), "r"(a.w), "r"(b.x), "r"(b.y))

template <int FMODE>
__global__ void __launch_bounds__(256) fused_mma(
    const float* __restrict__ xin, int mat,
    const float* __restrict__ bias1, const float* __restrict__ bias2,
    float* __restrict__ statsOut,
    const float* __restrict__ bnstats,
    const float* __restrict__ gammaL, const float* __restrict__ betaL,
    float* __restrict__ outP)
{
    extern __shared__ char smem[];
    float* sstat = (float*)(smem + 2 * A_MAT_BYTES);
    const int tid  = threadIdx.x;
    const int wid  = tid >> 5;
    const int lane = tid & 31;
    const int mbase = blockIdx.x * 128;
    const int warp_m = wid >> 1;
    const int warp_n = wid & 1;

    sstat[tid] = 0.f;

    if (FMODE != 2) {
        // ---- stage A: fp32 (+agg, BN affine of prev layer), split hi/lo, frag order ----
        const int rr  = tid >> 4;
        const int col = (tid & 15) * 8;
        const int ks  = col >> 4;
        const int p   = ((rr & 15) >= 8 ? 1 : 0) + (((col & 15) >= 8) ? 2 : 0);
        float sv[8], tv[8];
        if (bnstats) {
#pragma unroll
            for (int j = 0; j < 8; j++) {
                int c = col + j;
                float mean = __ldg(&bnstats[c]) * (1.0f / N_NODES);
                float var  = __ldg(&bnstats[DD + c]) * (1.0f / N_NODES) - mean * mean;
                float rstd = rsqrtf(var + BN_EPS);
                sv[j] = __ldg(&gammaL[c]) * rstd;
                tv[j] = __ldg(&betaL[c]) - mean * sv[j];
            }
        } else {
#pragma unroll
            for (int j = 0; j < 8; j++) { sv[j] = 1.f; tv[j] = 0.f; }
        }
#pragma unroll
        for (int msub = 0; msub < 8; msub++) {
            int m = mbase + msub * 16 + rr;
            float v[8];
            if (m < N_NODES) {
                size_t off = (size_t)m * DD + col;
                float4 p0 = *(const float4*)(xin + off);
                float4 p1 = *(const float4*)(xin + off + 4);
                float4 a0 = *(const float4*)(g_agg + off);
                float4 a1 = *(const float4*)(g_agg + off + 4);
                p0.x += a0.x; p0.y += a0.y; p0.z += a0.z; p0.w += a0.w;
                p1.x += a1.x; p1.y += a1.y; p1.z += a1.z; p1.w += a1.w;
                float cnt = 1.0f + (float)(g_off[m + 1] - g_off[m]);
                v[0] = sv[0] * p0.x + cnt * tv[0];
                v[1] = sv[1] * p0.y + cnt * tv[1];
                v[2] = sv[2] * p0.z + cnt * tv[2];
                v[3] = sv[3] * p0.w + cnt * tv[3];
                v[4] = sv[4] * p1.x + cnt * tv[4];
                v[5] = sv[5] * p1.y + cnt * tv[5];
                v[6] = sv[6] * p1.z + cnt * tv[6];
                v[7] = sv[7] * p1.w + cnt * tv[7];
            } else {
#pragma unroll
                for (int j = 0; j < 8; j++) v[j] = 0.f;
            }
            int frag = msub * 8 + ks;
            int fbase = frag * FRAG_STRIDE + p * 4;
            size_t gbase = ((size_t)blockIdx.x * 64 + frag) * 512 + p * 4;
#pragma unroll
            for (int j = 0; j < 4; j++) {
                float f0 = v[2 * j], f1 = v[2 * j + 1];
                uint32_t hb0 = bfbits(f0), hb1 = bfbits(f1);
                uint32_t hp = hb0 | (hb1 << 16);
                uint32_t lp = pack_bf2(f0 - bf2f((unsigned short)hb0),
                                       f1 - bf2f((unsigned short)hb1));
                int lane_w = (rr & 7) * 4 + j;
                *(uint32_t*)(smem + fbase + lane_w * 16)               = hp;
                *(uint32_t*)(smem + A_MAT_BYTES + fbase + lane_w * 16) = lp;
                if (FMODE == 1) {
                    *(uint32_t*)(&g_aimg[0][gbase + lane_w * 16]) = hp;
                    *(uint32_t*)(&g_aimg[1][gbase + lane_w * 16]) = lp;
                }
            }
        }
    }
    __syncthreads();

    float acc[2][8][4];

    // =========== MMA stage 1: A @ W1 ===========
#pragma unroll
    for (int i = 0; i < 2; i++)
#pragma unroll
        for (int j = 0; j < 8; j++)
#pragma unroll
            for (int q = 0; q < 4; q++) acc[i][j][q] = 0.f;
    {
        const uint2* wh = (const uint2*)&g_wimg[mat][0][0];
        const uint2* wl = (const uint2*)&g_wimg[mat][1][0];
#pragma unroll
        for (int k8 = 0; k8 < 8; k8++) {
            uint4 ah[2], al[2];
#pragma unroll
            for (int i = 0; i < 2; i++) {
                int frag = ((warp_m * 2 + i) * 8 + k8);
                if (FMODE == 2) {
                    size_t gb = ((size_t)blockIdx.x * 64 + frag) * 512 + lane * 16;
                    ah[i] = __ldg((const uint4*)&g_aimg[0][gb]);
                    al[i] = __ldg((const uint4*)&g_aimg[1][gb]);
                } else {
                    int fb = frag * FRAG_STRIDE + lane * 16;
                    ah[i] = *(const uint4*)(smem + fb);
                    al[i] = *(const uint4*)(smem + A_MAT_BYTES + fb);
                }
            }
            uint2 bh[8], bl[8];
#pragma unroll
            for (int ns = 0; ns < 8; ns++) {
                int bi = (k8 * 16 + warp_n * 8 + ns) * 32 + lane;
                bh[ns] = __ldg(&wh[bi]);
                bl[ns] = __ldg(&wl[bi]);
            }
#pragma unroll
            for (int ns = 0; ns < 8; ns++) {
                MMA_BF16(acc[0][ns], ah[0], bh[ns]);
                MMA_BF16(acc[1][ns], ah[1], bh[ns]);
                MMA_BF16(acc[0][ns], ah[0], bl[ns]);
                MMA_BF16(acc[1][ns], ah[1], bl[ns]);
                MMA_BF16(acc[0][ns], al[0], bh[ns]);
                MMA_BF16(acc[1][ns], al[1], bh[ns]);
            }
        }
    }

    // =========== convert h1 = relu(acc + b1) -> smem fragments (in place) ===========
    __syncthreads();   // all A reads done before overwrite
#pragma unroll
    for (int i = 0; i < 2; i++) {
#pragma unroll
        for (int ns = 0; ns < 8; ns++) {
            int c = warp_n * 64 + ns * 8 + (lane & 3) * 2;
            float2 bv = __ldg((const float2*)(bias1 + c));
            float o0 = fmaxf(acc[i][ns][0] + bv.x, 0.f);
            float o1 = fmaxf(acc[i][ns][1] + bv.y, 0.f);
            float o2 = fmaxf(acc[i][ns][2] + bv.x, 0.f);
            float o3 = fmaxf(acc[i][ns][3] + bv.y, 0.f);
            // fragment slot: frag rows = warp_m*2+i, ks = warp_n*4 + ns/2
            int frag = (warp_m * 2 + i) * 8 + warp_n * 4 + (ns >> 1);
            int base = frag * FRAG_STRIDE + lane * 16 + (ns & 1) * 8;
            uint32_t h01b0 = bfbits(o0), h01b1 = bfbits(o1);
            uint32_t h23b0 = bfbits(o2), h23b1 = bfbits(o3);
            *(uint32_t*)(smem + base)     = h01b0 | (h01b1 << 16);
            *(uint32_t*)(smem + base + 4) = h23b0 | (h23b1 << 16);
            *(uint32_t*)(smem + A_MAT_BYTES + base) =
                pack_bf2(o0 - bf2f((unsigned short)h01b0), o1 - bf2f((unsigned short)h01b1));
            *(uint32_t*)(smem + A_MAT_BYTES + base + 4) =
                pack_bf2(o2 - bf2f((unsigned short)h23b0), o3 - bf2f((unsigned short)h23b1));
        }
    }
    __syncthreads();

    // =========== MMA stage 2: h1 @ W2 ===========
#pragma unroll
    for (int i = 0; i < 2; i++)
#pragma unroll
        for (int j = 0; j < 8; j++)
#pragma unroll
            for (int q = 0; q < 4; q++) acc[i][j][q] = 0.f;
    {
        const uint2* wh = (const uint2*)&g_wimg[mat + 1][0][0];
        const uint2* wl = (const uint2*)&g_wimg[mat + 1][1][0];
#pragma unroll
        for (int k8 = 0; k8 < 8; k8++) {
            uint4 ah[2], al[2];
#pragma unroll
            for (int i = 0; i < 2; i++) {
                int fb = ((warp_m * 2 + i) * 8 + k8) * FRAG_STRIDE + lane * 16;
                ah[i] = *(const uint4*)(smem + fb);
                al[i] = *(const uint4*)(smem + A_MAT_BYTES + fb);
            }
            uint2 bh[8], bl[8];
#pragma unroll
            for (int ns = 0; ns < 8; ns++) {
                int bi = (k8 * 16 + warp_n * 8 + ns) * 32 + lane;
                bh[ns] = __ldg(&wh[bi]);
                bl[ns] = __ldg(&wl[bi]);
            }
#pragma unroll
            for (int ns = 0; ns < 8; ns++) {
                MMA_BF16(acc[0][ns], ah[0], bh[ns]);
                MMA_BF16(acc[1][ns], ah[1], bh[ns]);
                MMA_BF16(acc[0][ns], ah[0], bl[ns]);
                MMA_BF16(acc[1][ns], ah[1], bl[ns]);
                MMA_BF16(acc[0][ns], al[0], bh[ns]);
                MMA_BF16(acc[1][ns], al[1], bh[ns]);
            }
        }
    }

    // =========== epilogue: bias2 + act2 + store + fused BN stats ===========
    float* Out = (FMODE == 0) ? g_h2 : outP;
#pragma unroll
    for (int ns = 0; ns < 8; ns++) {
        int c = warp_n * 64 + ns * 8 + (lane & 3) * 2;
        float2 bv = __ldg((const float2*)(bias2 + c));
        float s0 = 0.f, s1 = 0.f, q0 = 0.f, q1 = 0.f;
#pragma unroll
        for (int i = 0; i < 2; i++) {
            int r0 = mbase + warp_m * 32 + i * 16 + (lane >> 2);
            float o0 = acc[i][ns][0] + bv.x;
            float o1 = acc[i][ns][1] + bv.y;
            float o2 = acc[i][ns][2] + bv.x;
            float o3 = acc[i][ns][3] + bv.y;
            if (FMODE == 0) {
                o0 = fmaxf(o0, 0.f); o1 = fmaxf(o1, 0.f);
                o2 = fmaxf(o2, 0.f); o3 = fmaxf(o3, 0.f);
            } else {
                o0 = tanhf(o0); o1 = tanhf(o1); o2 = tanhf(o2); o3 = tanhf(o3);
            }
            bool v0 = (r0 < N_NODES), v1 = (r0 + 8 < N_NODES);
            if (v0) *(float2*)(Out + (size_t)r0 * DD + c) = make_float2(o0, o1);
            if (v1) *(float2*)(Out + (size_t)(r0 + 8) * DD + c) = make_float2(o2, o3);
            if (v0) { s0 += o0; s1 += o1; q0 += o0 * o0; q1 += o1 * o1; }
            if (v1) { s0 += o2; s1 += o3; q0 += o2 * o2; q1 += o3 * o3; }
        }
#pragma unroll
        for (int off = 4; off <= 16; off <<= 1) {
            s0 += __shfl_xor_sync(0xffffffffu, s0, off);
            s1 += __shfl_xor_sync(0xffffffffu, s1, off);
            q0 += __shfl_xor_sync(0xffffffffu, q0, off);
            q1 += __shfl_xor_sync(0xffffffffu, q1, off);
        }
        if (lane < 4) {
            atomicAdd(&sstat[c],           s0);
            atomicAdd(&sstat[c + 1],       s1);
            atomicAdd(&sstat[128 + c],     q0);
            atomicAdd(&sstat[128 + c + 1], q1);
        }
    }
    __syncthreads();
    atomicAdd(&statsOut[tid], sstat[tid]);
}

// ================= fused batchnorm for 4 output layers (in-place on d_out) =================
__global__ void __launch_bounds__(256) bn4_kernel(
    float* __restrict__ outp,
    const float* __restrict__ gamma, const float* __restrict__ beta)
{
    __shared__ float sm_scale[4 * DD], sm_shift[4 * DD];
    int tid = threadIdx.x;
    for (int i = tid; i < 4 * DD; i += 256) {
        int L = i >> 7, c = i & 127;
        const float* st = g_statsL[3 + L];
        float mean = st[c] * (1.0f / N_NODES);
        float var  = st[DD + c] * (1.0f / N_NODES) - mean * mean;
        float rstd = rsqrtf(var + BN_EPS);
        float g = gamma[(3 + L) * DD + c], b = beta[(3 + L) * DD + c];
        sm_scale[i] = rstd * g;
        sm_shift[i] = b - mean * rstd * g;
    }
    __syncthreads();
    const int per_layer4 = N_NODES * DD / 4;
    int idx = blockIdx.x * 256 + tid;
    if (idx < 4 * per_layer4) {
        int L = idx / per_layer4;
        int w = idx - L * per_layer4;
        int c = L * DD + ((w * 4) & (DD - 1));
        float4 v = ((const float4*)outp)[idx];
        float4 r;
        r.x = v.x * sm_scale[c]     + sm_shift[c];
        r.y = v.y * sm_scale[c + 1] + sm_shift[c + 1];
        r.z = v.z * sm_scale[c + 2] + sm_shift[c + 2];
        r.w = v.w * sm_scale[c + 3] + sm_shift[c + 3];
        ((float4*)outp)[idx] = r;
    }
}

// ================= launcher =================
extern "C" void kernel_launch(void* const* d_in, const int* in_sizes, int n_in,
                              void* d_out, int out_size)
{
    const float* x     = (const float*)d_in[0];
    const int*   ei    = (const int*)d_in[1];     // int32 (JAX x64 disabled)
    const float* W1    = (const float*)d_in[3];
    const float* b1    = (const float*)d_in[4];
    const float* W2    = (const float*)d_in[5];
    const float* b2    = (const float*)d_in[6];
    const float* gamma = (const float*)d_in[7];
    const float* beta  = (const float*)d_in[8];
    float*       out   = (float*)d_out;

    const int* src = ei;
    const int* dst = ei + N_EDGES;

    cudaFuncSetAttribute(fused_mma<0>, cudaFuncAttributeMaxDynamicSharedMemorySize, SMEM_BYTES);
    cudaFuncSetAttribute(fused_mma<1>, cudaFuncAttributeMaxDynamicSharedMemorySize, SMEM_BYTES);
    cudaFuncSetAttribute(fused_mma<2>, cudaFuncAttributeMaxDynamicSharedMemorySize, SMEM_BYTES);

    float* statsBase = nullptr;
    cudaGetSymbolAddress((void**)&statsBase, g_statsL);
    float* h2p = nullptr;
    cudaGetSymbolAddress((void**)&h2p, g_h2);

    const int EG = (N_EDGES + 255) / 256;
    const int NG = (N_NODES + 255) / 256;
    const int AG = (N_NODES * 32 + 255) / 256;
    const int GG = NTILES;
    const int WG = (14 * DD * DD + 255) / 256;
    const int B4 = (4 * N_NODES * DD / 4 + 255) / 256;

    // one-time per-call prep
    zero_cnt_kernel<<<NG, 256>>>();
    hist_kernel<<<EG, 256>>>(dst);
    wconv_kernel<<<WG, 256>>>(W1, W2);
    scan1_kernel<<<NG, 256>>>();
    scan2_kernel<<<1, 256>>>(NG);
    scan3_kernel<<<NG, 256>>>();
    fill_kernel<<<EG, 256>>>(src, dst);

    // ---- GC layers 0-2: agg + fused dual-GEMM (prev BN folded into staging) ----
    for (int l = 0; l < 3; l++) {
        const float* xin = (l == 0) ? x : h2p;
        const float* bnst = (l == 0) ? nullptr : statsBase + (l - 1) * 2 * DD;
        agg_kernel<<<AG, 256>>>(xin);
        fused_mma<0><<<GG, 256, SMEM_BYTES>>>(
            xin, l * 2, b1 + (size_t)l * DD, b2 + (size_t)l * DD,
            statsBase + l * 2 * DD, bnst,
            gamma + (size_t)(l - 1) * DD, beta + (size_t)(l - 1) * DD, nullptr);
    }

    // ---- output layers 3-6: shared input/agg; fused dual-GEMM -> d_out ----
    agg_kernel<<<AG, 256>>>(h2p);
    for (int l = 3; l < 7; l++) {
        float* op = out + (size_t)(l - 3) * N_NODES * DD;
        if (l == 3)
            fused_mma<1><<<GG, 256, SMEM_BYTES>>>(
                h2p, l * 2, b1 + (size_t)l * DD, b2 + (size_t)l * DD,
                statsBase + l * 2 * DD, statsBase + 2 * 2 * DD,
                gamma + (size_t)2 * DD, beta + (size_t)2 * DD, op);
        else
            fused_mma<2><<<GG, 256, SMEM_BYTES>>>(
                nullptr, l * 2, b1 + (size_t)l * DD, b2 + (size_t)l * DD,
                statsBase + l * 2 * DD, nullptr, nullptr, nullptr, op);
    }
    bn4_kernel<<<B4, 256>>>(out, gamma, beta);
}